// round 3
// baseline (speedup 1.0000x reference)
#include <cuda_runtime.h>
#include <cstdint>
#include <cstddef>

#define NL 6
#define D 1024
#define H 16
#define FF 4096
#define NB 33
#define DH 64
#define BB 4
#define SS 1024
#define BS (BB*SS)   // 4096

// ---------------- scratch (device globals; no allocation) ----------------
__device__ float g_q[BS*D];
__device__ float g_k[BS*D];
__device__ float g_v[BS*D];
__device__ float g_a[BS*D];
__device__ float g_t[BS*D];
__device__ float g_ffin[BS*D];
__device__ float g_x[BS*D];
__device__ float g_h[(size_t)BS*FF];
__device__ float g_qE[(size_t)BB*H*SS*NB];

// ---------------- generic tiled FP32 GEMM: C = A[MxK] @ B[KxN] + bias (+res)(+relu) ----------------
// gridDim.z selects among up to 3 (B, bias, C) sets for fused QKV.
__global__ __launch_bounds__(256) void gemm128(
    const float* __restrict__ A,
    const float* __restrict__ B0, const float* __restrict__ B1, const float* __restrict__ B2,
    const float* __restrict__ bias0, const float* __restrict__ bias1, const float* __restrict__ bias2,
    const float* __restrict__ res,
    float* __restrict__ C0, float* __restrict__ C1, float* __restrict__ C2,
    int M, int N, int K, int relu)
{
    const float* Bm  = (blockIdx.z == 0) ? B0 : (blockIdx.z == 1 ? B1 : B2);
    const float* bias = (blockIdx.z == 0) ? bias0 : (blockIdx.z == 1 ? bias1 : bias2);
    float* C = (blockIdx.z == 0) ? C0 : (blockIdx.z == 1 ? C1 : C2);

    __shared__ float As[16][128];   // transposed: As[k][m]
    __shared__ float Bs[16][128];   // Bs[k][n]
    int bm = blockIdx.y * 128, bn = blockIdx.x * 128;
    int tid = threadIdx.x;
    int tx = tid & 15, ty = tid >> 4;

    float acc[8][8];
#pragma unroll
    for (int i = 0; i < 8; i++)
#pragma unroll
        for (int j = 0; j < 8; j++) acc[i][j] = 0.f;

    for (int k0 = 0; k0 < K; k0 += 16) {
#pragma unroll
        for (int u = 0; u < 2; u++) {
            int f = tid + u * 256;            // 0..511
            int row = f >> 2;                 // 0..127
            int kc = (f & 3) << 2;            // 0,4,8,12
            float4 va = *(const float4*)(A + (size_t)(bm + row) * K + k0 + kc);
            As[kc + 0][row] = va.x; As[kc + 1][row] = va.y;
            As[kc + 2][row] = va.z; As[kc + 3][row] = va.w;
            int rb = f >> 5;                  // 0..15
            int nc = (f & 31) << 2;           // 0..124
            *(float4*)(&Bs[rb][nc]) = *(const float4*)(Bm + (size_t)(k0 + rb) * N + bn + nc);
        }
        __syncthreads();
#pragma unroll
        for (int kk = 0; kk < 16; kk++) {
            float a[8], b[8];
            *(float4*)(a)     = *(float4*)(&As[kk][ty * 8]);
            *(float4*)(a + 4) = *(float4*)(&As[kk][ty * 8 + 4]);
            *(float4*)(b)     = *(float4*)(&Bs[kk][tx * 8]);
            *(float4*)(b + 4) = *(float4*)(&Bs[kk][tx * 8 + 4]);
#pragma unroll
            for (int i = 0; i < 8; i++)
#pragma unroll
                for (int j = 0; j < 8; j++) acc[i][j] += a[i] * b[j];
        }
        __syncthreads();
    }

#pragma unroll
    for (int i = 0; i < 8; i++) {
        int m = bm + ty * 8 + i;
#pragma unroll
        for (int j = 0; j < 8; j += 4) {
            int n = bn + tx * 8 + j;
            float4 c;
            c.x = acc[i][j + 0] + bias[n + 0];
            c.y = acc[i][j + 1] + bias[n + 1];
            c.z = acc[i][j + 2] + bias[n + 2];
            c.w = acc[i][j + 3] + bias[n + 3];
            if (res) {
                float4 r = *(const float4*)(res + (size_t)m * N + n);
                c.x += r.x; c.y += r.y; c.z += r.z; c.w += r.w;
            }
            if (relu) {
                c.x = fmaxf(c.x, 0.f); c.y = fmaxf(c.y, 0.f);
                c.z = fmaxf(c.z, 0.f); c.w = fmaxf(c.w, 0.f);
            }
            *(float4*)(C + (size_t)m * N + n) = c;
        }
    }
}

// ---------------- qE[b,h,s,nb] = sum_d q[b,s,h*64+d] * Erel[nb,d] ----------------
__global__ __launch_bounds__(256) void qe_kernel(
    const float* __restrict__ Q, const float* __restrict__ Erel,
    float* __restrict__ qE)
{
    __shared__ float qrow[D];
    __shared__ float er[NB * DH];
    int bs = blockIdx.x;                // b*S + s
    int b = bs >> 10, s = bs & 1023;
    for (int i = threadIdx.x; i < D / 4; i += 256)
        ((float4*)qrow)[i] = ((const float4*)(Q + (size_t)bs * D))[i];
    for (int i = threadIdx.x; i < NB * DH / 4; i += 256)
        ((float4*)er)[i] = ((const float4*)Erel)[i];
    __syncthreads();
    for (int idx = threadIdx.x; idx < H * NB; idx += 256) {
        int h = idx / NB, nb = idx % NB;
        float acc = 0.f;
#pragma unroll 16
        for (int d = 0; d < DH; d++) acc += qrow[h * DH + d] * er[nb * DH + d];
        qE[(((size_t)(b * H + h)) * SS + s) * NB + nb] = acc;
    }
}

// ---------------- flash attention with rel-e / rel-b gathers ----------------
#define ATT_SMEM_FLOATS (4*64*68 + 64*NB + 64)
__global__ __launch_bounds__(256) void attn_kernel(
    const float* __restrict__ Q, const float* __restrict__ Kg,
    const float* __restrict__ Vg, const float* __restrict__ qE,
    const float* __restrict__ Brel, const int* __restrict__ rid,
    float* __restrict__ O)
{
    extern __shared__ float sm[];
    float* sQT = sm;                  // [d][68]   (d-major, 64 rows)
    float* sKT = sQT + 64 * 68;       // [d][68]
    float* sV  = sKT + 64 * 68;       // [kk][68]
    float* sPT = sV  + 64 * 68;       // [col][68] (col-major P)
    float* sQE = sPT + 64 * 68;       // [row][NB]
    float* sB  = sQE + 64 * NB;       // [NB]

    int qb = blockIdx.x, h = blockIdx.y, b = blockIdx.z;
    int tid = threadIdx.x;
    int tx = tid & 15, ty = tid >> 4;
    int q0 = qb * 64;

    const float* Qb = Q + ((size_t)(b * SS) + q0) * D + h * DH;
    for (int i = tid; i < 64 * 16; i += 256) {
        int row = i >> 4;
        int c4 = (i & 15) << 2;
        float4 v = *(const float4*)(Qb + (size_t)row * D + c4);
        sQT[(c4 + 0) * 68 + row] = v.x; sQT[(c4 + 1) * 68 + row] = v.y;
        sQT[(c4 + 2) * 68 + row] = v.z; sQT[(c4 + 3) * 68 + row] = v.w;
    }
    const float* qEb = qE + (((size_t)(b * H + h)) * SS + q0) * NB;
    for (int i = tid; i < (64 * NB) / 4; i += 256)
        ((float4*)sQE)[i] = ((const float4*)qEb)[i];
    for (int i = tid; i < NB; i += 256) sB[i] = Brel[h * NB + i];

    float m_run[4], l_run[4], acc[4][4];
#pragma unroll
    for (int i = 0; i < 4; i++) {
        m_run[i] = -1e30f; l_run[i] = 0.f;
#pragma unroll
        for (int j = 0; j < 4; j++) acc[i][j] = 0.f;
    }

    for (int kb = 0; kb < 16; kb++) {
        __syncthreads();   // prev iter's sKT/sV/sPT reads done; also covers Q/qE loads on kb=0
        int k0 = kb * 64;
        const float* Kb = Kg + ((size_t)(b * SS) + k0) * D + h * DH;
        const float* Vb = Vg + ((size_t)(b * SS) + k0) * D + h * DH;
        for (int i = tid; i < 64 * 16; i += 256) {
            int row = i >> 4;
            int c4 = (i & 15) << 2;
            float4 v = *(const float4*)(Kb + (size_t)row * D + c4);
            sKT[(c4 + 0) * 68 + row] = v.x; sKT[(c4 + 1) * 68 + row] = v.y;
            sKT[(c4 + 2) * 68 + row] = v.z; sKT[(c4 + 3) * 68 + row] = v.w;
            float4 w = *(const float4*)(Vb + (size_t)row * D + c4);
            *(float4*)(&sV[row * 68 + c4]) = w;
        }
        __syncthreads();

        // scores: 4x4 microtile per thread
        float s[4][4];
#pragma unroll
        for (int i = 0; i < 4; i++)
#pragma unroll
            for (int j = 0; j < 4; j++) s[i][j] = 0.f;
#pragma unroll 8
        for (int d = 0; d < 64; d++) {
            float4 a4 = *(float4*)(&sQT[d * 68 + ty * 4]);
            float4 b4 = *(float4*)(&sKT[d * 68 + tx * 4]);
            float a[4] = {a4.x, a4.y, a4.z, a4.w};
            float bb[4] = {b4.x, b4.y, b4.z, b4.w};
#pragma unroll
            for (int i = 0; i < 4; i++)
#pragma unroll
                for (int j = 0; j < 4; j++) s[i][j] += a[i] * bb[j];
        }
        // rel-e gather + rel-b gather + scale
#pragma unroll
        for (int i = 0; i < 4; i++) {
            int qrow = ty * 4 + i;
            const int* rr = rid + (size_t)(q0 + qrow) * SS + k0 + tx * 4;
#pragma unroll
            for (int j = 0; j < 4; j++) {
                int id = rr[j];
                s[i][j] = (s[i][j] + sQE[qrow * NB + id] + sB[id]) * 0.125f;
            }
        }
        // online softmax (row stats across the 16 tx-lanes)
#pragma unroll
        for (int i = 0; i < 4; i++) {
            float mx = fmaxf(fmaxf(s[i][0], s[i][1]), fmaxf(s[i][2], s[i][3]));
#pragma unroll
            for (int o = 1; o < 16; o <<= 1) mx = fmaxf(mx, __shfl_xor_sync(0xffffffffu, mx, o));
            float m_new = fmaxf(m_run[i], mx);
            float alpha = __expf(m_run[i] - m_new);
            m_run[i] = m_new;
            float rs = 0.f;
#pragma unroll
            for (int j = 0; j < 4; j++) { s[i][j] = __expf(s[i][j] - m_new); rs += s[i][j]; }
#pragma unroll
            for (int o = 1; o < 16; o <<= 1) rs += __shfl_xor_sync(0xffffffffu, rs, o);
            l_run[i] = l_run[i] * alpha + rs;
#pragma unroll
            for (int j = 0; j < 4; j++) acc[i][j] *= alpha;
        }
        // store P transposed (col-major) for the PV stage
#pragma unroll
        for (int j = 0; j < 4; j++) {
            float4 pv; pv.x = s[0][j]; pv.y = s[1][j]; pv.z = s[2][j]; pv.w = s[3][j];
            *(float4*)(&sPT[(tx * 4 + j) * 68 + ty * 4]) = pv;
        }
        __syncthreads();
        // PV accumulate
#pragma unroll 8
        for (int kk = 0; kk < 64; kk++) {
            float4 a4 = *(float4*)(&sPT[kk * 68 + ty * 4]);
            float4 b4 = *(float4*)(&sV[kk * 68 + tx * 4]);
            float a[4] = {a4.x, a4.y, a4.z, a4.w};
            float bb[4] = {b4.x, b4.y, b4.z, b4.w};
#pragma unroll
            for (int i = 0; i < 4; i++)
#pragma unroll
                for (int j = 0; j < 4; j++) acc[i][j] += a[i] * bb[j];
        }
    }
    // write O[b, q, h*64 + c]  (bqhd layout)
#pragma unroll
    for (int i = 0; i < 4; i++) {
        float inv = 1.f / l_run[i];
        int qrow = q0 + ty * 4 + i;
        float4 c;
        c.x = acc[i][0] * inv; c.y = acc[i][1] * inv;
        c.z = acc[i][2] * inv; c.w = acc[i][3] * inv;
        *(float4*)(O + ((size_t)(b * SS) + qrow) * D + h * DH + tx * 4) = c;
    }
}

// ---------------- LayerNorm over last dim (1024), one block per row ----------------
__global__ __launch_bounds__(256) void ln_kernel(
    const float* __restrict__ X, const float* __restrict__ g,
    const float* __restrict__ be, float* __restrict__ Y)
{
    __shared__ float ss[8], ssq[8];
    int row = blockIdx.x;
    int tid = threadIdx.x;
    const float* x = X + (size_t)row * D;
    float4 v = ((const float4*)x)[tid];
    float s = v.x + v.y + v.z + v.w;
    float sq = v.x * v.x + v.y * v.y + v.z * v.z + v.w * v.w;
#pragma unroll
    for (int o = 16; o; o >>= 1) {
        s += __shfl_xor_sync(0xffffffffu, s, o);
        sq += __shfl_xor_sync(0xffffffffu, sq, o);
    }
    int w = tid >> 5;
    if ((tid & 31) == 0) { ss[w] = s; ssq[w] = sq; }
    __syncthreads();
    if (tid < 32) {
        s = (tid < 8) ? ss[tid] : 0.f;
        sq = (tid < 8) ? ssq[tid] : 0.f;
#pragma unroll
        for (int o = 4; o; o >>= 1) {
            s += __shfl_xor_sync(0xffffffffu, s, o);
            sq += __shfl_xor_sync(0xffffffffu, sq, o);
        }
        if (tid == 0) { ss[0] = s; ssq[0] = sq; }
    }
    __syncthreads();
    float mean = ss[0] * (1.f / D);
    float var = ssq[0] * (1.f / D) - mean * mean;
    float inv = rsqrtf(var + 1e-6f);
    float4 gg = ((const float4*)g)[tid];
    float4 bb = ((const float4*)be)[tid];
    float4 o;
    o.x = (v.x - mean) * inv * gg.x + bb.x;
    o.y = (v.y - mean) * inv * gg.y + bb.y;
    o.z = (v.z - mean) * inv * gg.z + bb.z;
    o.w = (v.w - mean) * inv * gg.w + bb.w;
    ((float4*)(Y + (size_t)row * D))[tid] = o;
}

// ---------------- host orchestration ----------------
extern "C" void kernel_launch(void* const* d_in, const int* in_sizes, int n_in,
                              void* d_out, int out_size)
{
    const float* x_in = (const float*)d_in[0];
    const int*   rid  = (const int*)d_in[1];
    const float* Wq = (const float*)d_in[2];
    const float* bq = (const float*)d_in[3];
    const float* Wk = (const float*)d_in[4];
    const float* bk = (const float*)d_in[5];
    const float* Wv = (const float*)d_in[6];
    const float* bv = (const float*)d_in[7];
    const float* Wo = (const float*)d_in[8];
    const float* bo = (const float*)d_in[9];
    const float* Erel = (const float*)d_in[10];
    const float* Brel = (const float*)d_in[11];
    const float* g1  = (const float*)d_in[12];
    const float* be1 = (const float*)d_in[13];
    const float* g2  = (const float*)d_in[14];
    const float* be2 = (const float*)d_in[15];
    const float* W1 = (const float*)d_in[16];
    const float* b1 = (const float*)d_in[17];
    const float* W2 = (const float*)d_in[18];
    const float* b2 = (const float*)d_in[19];

    float *q, *k, *v, *a, *t, *ffin, *xg, *hh, *qe;
    cudaGetSymbolAddress((void**)&q, g_q);
    cudaGetSymbolAddress((void**)&k, g_k);
    cudaGetSymbolAddress((void**)&v, g_v);
    cudaGetSymbolAddress((void**)&a, g_a);
    cudaGetSymbolAddress((void**)&t, g_t);
    cudaGetSymbolAddress((void**)&ffin, g_ffin);
    cudaGetSymbolAddress((void**)&xg, g_x);
    cudaGetSymbolAddress((void**)&hh, g_h);
    cudaGetSymbolAddress((void**)&qe, g_qE);

    size_t att_smem = (size_t)ATT_SMEM_FLOATS * sizeof(float);
    cudaFuncSetAttribute(attn_kernel, cudaFuncAttributeMaxDynamicSharedMemorySize, (int)att_smem);

    const float* X = x_in;
    for (int l = 0; l < NL; l++) {
        const size_t wDD = (size_t)l * D * D;
        // fused QKV: one launch, z selects {q,k,v}
        gemm128<<<dim3(8, 32, 3), 256>>>(X,
            Wq + wDD, Wk + wDD, Wv + wDD,
            bq + l * D, bk + l * D, bv + l * D,
            nullptr, q, k, v, BS, D, D, 0);
        qe_kernel<<<BS, 256>>>(q, Erel + (size_t)l * NB * DH, qe);
        attn_kernel<<<dim3(16, 16, 4), 256, att_smem>>>(q, k, v, qe, Brel + (size_t)l * H * NB, rid, a);
        gemm128<<<dim3(8, 32, 1), 256>>>(a, Wo + wDD, nullptr, nullptr,
            bo + l * D, nullptr, nullptr, X, t, nullptr, nullptr, BS, D, D, 0);
        ln_kernel<<<BS, 256>>>(t, g1 + l * D, be1 + l * D, ffin);
        gemm128<<<dim3(32, 32, 1), 256>>>(ffin, W1 + (size_t)l * D * FF, nullptr, nullptr,
            b1 + (size_t)l * FF, nullptr, nullptr, nullptr, hh, nullptr, nullptr, BS, FF, D, 1);
        gemm128<<<dim3(8, 32, 1), 256>>>(hh, W2 + (size_t)l * FF * D, nullptr, nullptr,
            b2 + l * D, nullptr, nullptr, ffin, t, nullptr, nullptr, BS, D, FF, 0);
        float* out = (l == NL - 1) ? (float*)d_out : xg;
        ln_kernel<<<BS, 256>>>(t, g2 + l * D, be2 + l * D, out);
        X = xg;
    }
}

// round 5
// speedup vs baseline: 1.8290x; 1.8290x over previous
#include <cuda_runtime.h>
#include <cuda_bf16.h>
#include <cstdint>
#include <cstddef>

#define NL 6
#define D 1024
#define H 16
#define FF 4096
#define NB 33
#define DH 64
#define BB 4
#define SS 1024
#define BS (BB*SS)   // 4096

// ---------------- scratch (device globals; no allocation) ----------------
__device__ float g_q[BS*D];
__device__ float g_k[BS*D];
__device__ float g_v[BS*D];
__device__ float g_a[BS*D];
__device__ float g_t[BS*D];
__device__ float g_ffin[BS*D];
__device__ float g_x[BS*D];
__device__ float g_h[(size_t)BS*FF];
__device__ float g_qE[(size_t)BB*H*SS*NB];

// ---------------- helpers ----------------
__device__ __forceinline__ uint32_t smem_u32(const void* p) {
    return (uint32_t)__cvta_generic_to_shared(p);
}
__device__ __forceinline__ uint32_t pack_hi2(float a, float b) {
    __nv_bfloat162 t = __floats2bfloat162_rn(a, b);
    return *reinterpret_cast<uint32_t*>(&t);
}
__device__ __forceinline__ uint32_t pack_lo2(float a, float b) {
    float ra = a - __bfloat162float(__float2bfloat16(a));
    float rb = b - __bfloat162float(__float2bfloat16(b));
    __nv_bfloat162 t = __floats2bfloat162_rn(ra, rb);
    return *reinterpret_cast<uint32_t*>(&t);
}
__device__ __forceinline__ void ldmx4(uint32_t* r, uint32_t addr) {
    asm volatile("ldmatrix.sync.aligned.m8n8.x4.shared.b16 {%0,%1,%2,%3}, [%4];"
                 : "=r"(r[0]), "=r"(r[1]), "=r"(r[2]), "=r"(r[3]) : "r"(addr));
}
__device__ __forceinline__ void ldmx2t(uint32_t* r, uint32_t addr) {
    asm volatile("ldmatrix.sync.aligned.m8n8.x2.trans.shared.b16 {%0,%1}, [%2];"
                 : "=r"(r[0]), "=r"(r[1]) : "r"(addr));
}
__device__ __forceinline__ void mma16816(float* c, const uint32_t* a, const uint32_t* b) {
    asm volatile("mma.sync.aligned.m16n8k16.row.col.f32.bf16.bf16.f32 "
                 "{%0,%1,%2,%3}, {%4,%5,%6,%7}, {%8,%9}, {%0,%1,%2,%3};"
                 : "+f"(c[0]), "+f"(c[1]), "+f"(c[2]), "+f"(c[3])
                 : "r"(a[0]), "r"(a[1]), "r"(a[2]), "r"(a[3]), "r"(b[0]), "r"(b[1]));
}

// ---------------- tensor-core GEMM (split-bf16 x3): C = A[MxK] @ B[KxN] + bias (+res)(+relu) ----------------
// gridDim.z selects among up to 3 (B, bias, C) sets for fused QKV.
// Tiles: 128x128 block, k-block 32; 8 warps in 2(M)x4(N); warp tile 64x32; mma m16n8k16.
// Row strides MUST be multiples of 8 bf16 (16B) for ldmatrix alignment:
//   APAD=40  -> 80B stride  (rows mod 128B: 0,80,32,112,64,16,96,48 -> conflict-free)
//   BPAD=136 -> 272B stride (mod 128B = 16 -> 8 k-rows hit 8 distinct 16B offsets)
#define APAD 40
#define BPAD 136
__global__ __launch_bounds__(256) void gemm_tc(
    const float* __restrict__ A,
    const float* __restrict__ B0, const float* __restrict__ B1, const float* __restrict__ B2,
    const float* __restrict__ bias0, const float* __restrict__ bias1, const float* __restrict__ bias2,
    const float* __restrict__ res,
    float* __restrict__ C0, float* __restrict__ C1, float* __restrict__ C2,
    int M, int N, int K, int relu)
{
    const float* Bm   = (blockIdx.z == 0) ? B0 : (blockIdx.z == 1 ? B1 : B2);
    const float* bias = (blockIdx.z == 0) ? bias0 : (blockIdx.z == 1 ? bias1 : bias2);
    float* C          = (blockIdx.z == 0) ? C0 : (blockIdx.z == 1 ? C1 : C2);

    __shared__ __nv_bfloat16 Ah[128][APAD], Al[128][APAD];
    __shared__ __nv_bfloat16 Bh[32][BPAD],  Bl[32][BPAD];

    int bm = blockIdx.y * 128, bn = blockIdx.x * 128;
    int tid = threadIdx.x;
    int lane = tid & 31, wid = tid >> 5;
    int wm = (wid >> 2) * 64;      // warp M offset within block
    int wn = (wid & 3) * 32;       // warp N offset within block

    float acc[4][4][4];
#pragma unroll
    for (int i = 0; i < 4; i++)
#pragma unroll
        for (int j = 0; j < 4; j++)
#pragma unroll
            for (int t = 0; t < 4; t++) acc[i][j][t] = 0.f;

    for (int k0b = 0; k0b < K; k0b += 32) {
        // ---- load + split A tile (128 x 32) ----
#pragma unroll
        for (int u = 0; u < 4; u++) {
            int f = tid + u * 256;          // 0..1023
            int row = f >> 3;               // 0..127
            int kc = (f & 7) << 2;          // 0,4,...,28
            float4 v = *(const float4*)(A + (size_t)(bm + row) * K + k0b + kc);
            *(uint32_t*)(&Ah[row][kc])     = pack_hi2(v.x, v.y);
            *(uint32_t*)(&Ah[row][kc + 2]) = pack_hi2(v.z, v.w);
            *(uint32_t*)(&Al[row][kc])     = pack_lo2(v.x, v.y);
            *(uint32_t*)(&Al[row][kc + 2]) = pack_lo2(v.z, v.w);
        }
        // ---- load + split B tile (32 x 128) ----
#pragma unroll
        for (int u = 0; u < 4; u++) {
            int f = tid + u * 256;
            int kr = f >> 5;                // 0..31
            int nc = (f & 31) << 2;         // 0..124
            float4 v = *(const float4*)(Bm + (size_t)(k0b + kr) * N + bn + nc);
            *(uint32_t*)(&Bh[kr][nc])     = pack_hi2(v.x, v.y);
            *(uint32_t*)(&Bh[kr][nc + 2]) = pack_hi2(v.z, v.w);
            *(uint32_t*)(&Bl[kr][nc])     = pack_lo2(v.x, v.y);
            *(uint32_t*)(&Bl[kr][nc + 2]) = pack_lo2(v.z, v.w);
        }
        __syncthreads();

#pragma unroll
        for (int h = 0; h < 2; h++) {       // two k16 halves
            int k0 = h * 16;
            // B fragments for all 4 nj
            uint32_t bhf[4][2], blf[4][2];
            int brow = k0 + (lane & 15);
#pragma unroll
            for (int nj = 0; nj < 4; nj++) {
                uint32_t ab = smem_u32(&Bh[brow][wn + nj * 8]);
                ldmx2t(bhf[nj], ab);
                uint32_t al_ = smem_u32(&Bl[brow][wn + nj * 8]);
                ldmx2t(blf[nj], al_);
            }
#pragma unroll
            for (int mi = 0; mi < 4; mi++) {
                int arow = wm + mi * 16 + (lane & 15);
                int acol = k0 + ((lane >> 4) << 3);
                uint32_t ah[4], al[4];
                ldmx4(ah, smem_u32(&Ah[arow][acol]));
                ldmx4(al, smem_u32(&Al[arow][acol]));
#pragma unroll
                for (int nj = 0; nj < 4; nj++) {
                    mma16816(acc[mi][nj], ah, bhf[nj]);   // hi*hi
                    mma16816(acc[mi][nj], ah, blf[nj]);   // hi*lo
                    mma16816(acc[mi][nj], al, bhf[nj]);   // lo*hi
                }
            }
        }
        __syncthreads();
    }

    // ---- epilogue ----
#pragma unroll
    for (int mi = 0; mi < 4; mi++) {
#pragma unroll
        for (int nj = 0; nj < 4; nj++) {
            int r0 = bm + wm + mi * 16 + (lane >> 2);
            int c0 = bn + wn + nj * 8 + (lane & 3) * 2;
#pragma unroll
            for (int half = 0; half < 2; half++) {
                int r = r0 + half * 8;
                float o0 = acc[mi][nj][half * 2 + 0] + bias[c0];
                float o1 = acc[mi][nj][half * 2 + 1] + bias[c0 + 1];
                if (res) {
                    float2 rr = *(const float2*)(res + (size_t)r * N + c0);
                    o0 += rr.x; o1 += rr.y;
                }
                if (relu) { o0 = fmaxf(o0, 0.f); o1 = fmaxf(o1, 0.f); }
                float2 o; o.x = o0; o.y = o1;
                *(float2*)(C + (size_t)r * N + c0) = o;
            }
        }
    }
}

// ---------------- qE[b,h,s,nb] = sum_d q[b,s,h*64+d] * Erel[nb,d] ----------------
__global__ __launch_bounds__(256) void qe_kernel(
    const float* __restrict__ Q, const float* __restrict__ Erel,
    float* __restrict__ qE)
{
    __shared__ float qrow[D];
    __shared__ float er[NB * DH];
    int bs = blockIdx.x;                // b*S + s
    int b = bs >> 10, s = bs & 1023;
    for (int i = threadIdx.x; i < D / 4; i += 256)
        ((float4*)qrow)[i] = ((const float4*)(Q + (size_t)bs * D))[i];
    for (int i = threadIdx.x; i < NB * DH / 4; i += 256)
        ((float4*)er)[i] = ((const float4*)Erel)[i];
    __syncthreads();
    for (int idx = threadIdx.x; idx < H * NB; idx += 256) {
        int h = idx / NB, nb = idx % NB;
        float acc = 0.f;
#pragma unroll 16
        for (int d = 0; d < DH; d++) acc += qrow[h * DH + d] * er[nb * DH + d];
        qE[(((size_t)(b * H + h)) * SS + s) * NB + nb] = acc;
    }
}

// ---------------- flash attention with rel-e / rel-b gathers ----------------
#define ATT_SMEM_FLOATS (4*64*68 + 64*NB + 64)
__global__ __launch_bounds__(256) void attn_kernel(
    const float* __restrict__ Q, const float* __restrict__ Kg,
    const float* __restrict__ Vg, const float* __restrict__ qE,
    const float* __restrict__ Brel, const int* __restrict__ rid,
    float* __restrict__ O)
{
    extern __shared__ float sm[];
    float* sQT = sm;                  // [d][68]   (d-major, 64 rows)
    float* sKT = sQT + 64 * 68;       // [d][68]
    float* sV  = sKT + 64 * 68;       // [kk][68]
    float* sPT = sV  + 64 * 68;       // [col][68] (col-major P)
    float* sQE = sPT + 64 * 68;       // [row][NB]
    float* sB  = sQE + 64 * NB;       // [NB]

    int qb = blockIdx.x, h = blockIdx.y, b = blockIdx.z;
    int tid = threadIdx.x;
    int tx = tid & 15, ty = tid >> 4;
    int q0 = qb * 64;

    const float* Qb = Q + ((size_t)(b * SS) + q0) * D + h * DH;
    for (int i = tid; i < 64 * 16; i += 256) {
        int row = i >> 4;
        int c4 = (i & 15) << 2;
        float4 v = *(const float4*)(Qb + (size_t)row * D + c4);
        sQT[(c4 + 0) * 68 + row] = v.x; sQT[(c4 + 1) * 68 + row] = v.y;
        sQT[(c4 + 2) * 68 + row] = v.z; sQT[(c4 + 3) * 68 + row] = v.w;
    }
    const float* qEb = qE + (((size_t)(b * H + h)) * SS + q0) * NB;
    for (int i = tid; i < (64 * NB) / 4; i += 256)
        ((float4*)sQE)[i] = ((const float4*)qEb)[i];
    for (int i = tid; i < NB; i += 256) sB[i] = Brel[h * NB + i];

    float m_run[4], l_run[4], acc[4][4];
#pragma unroll
    for (int i = 0; i < 4; i++) {
        m_run[i] = -1e30f; l_run[i] = 0.f;
#pragma unroll
        for (int j = 0; j < 4; j++) acc[i][j] = 0.f;
    }

    for (int kb = 0; kb < 16; kb++) {
        __syncthreads();   // prev iter's sKT/sV/sPT reads done; also covers Q/qE loads on kb=0
        int k0 = kb * 64;
        const float* Kb = Kg + ((size_t)(b * SS) + k0) * D + h * DH;
        const float* Vb = Vg + ((size_t)(b * SS) + k0) * D + h * DH;
        for (int i = tid; i < 64 * 16; i += 256) {
            int row = i >> 4;
            int c4 = (i & 15) << 2;
            float4 v = *(const float4*)(Kb + (size_t)row * D + c4);
            sKT[(c4 + 0) * 68 + row] = v.x; sKT[(c4 + 1) * 68 + row] = v.y;
            sKT[(c4 + 2) * 68 + row] = v.z; sKT[(c4 + 3) * 68 + row] = v.w;
            float4 w = *(const float4*)(Vb + (size_t)row * D + c4);
            *(float4*)(&sV[row * 68 + c4]) = w;
        }
        __syncthreads();

        // scores: 4x4 microtile per thread
        float s[4][4];
#pragma unroll
        for (int i = 0; i < 4; i++)
#pragma unroll
            for (int j = 0; j < 4; j++) s[i][j] = 0.f;
#pragma unroll 8
        for (int d = 0; d < 64; d++) {
            float4 a4 = *(float4*)(&sQT[d * 68 + ty * 4]);
            float4 b4 = *(float4*)(&sKT[d * 68 + tx * 4]);
            float a[4] = {a4.x, a4.y, a4.z, a4.w};
            float bb[4] = {b4.x, b4.y, b4.z, b4.w};
#pragma unroll
            for (int i = 0; i < 4; i++)
#pragma unroll
                for (int j = 0; j < 4; j++) s[i][j] += a[i] * bb[j];
        }
        // rel-e gather + rel-b gather + scale
#pragma unroll
        for (int i = 0; i < 4; i++) {
            int qrow = ty * 4 + i;
            const int* rr = rid + (size_t)(q0 + qrow) * SS + k0 + tx * 4;
#pragma unroll
            for (int j = 0; j < 4; j++) {
                int id = rr[j];
                s[i][j] = (s[i][j] + sQE[qrow * NB + id] + sB[id]) * 0.125f;
            }
        }
        // online softmax (row stats across the 16 tx-lanes)
#pragma unroll
        for (int i = 0; i < 4; i++) {
            float mx = fmaxf(fmaxf(s[i][0], s[i][1]), fmaxf(s[i][2], s[i][3]));
#pragma unroll
            for (int o = 1; o < 16; o <<= 1) mx = fmaxf(mx, __shfl_xor_sync(0xffffffffu, mx, o));
            float m_new = fmaxf(m_run[i], mx);
            float alpha = __expf(m_run[i] - m_new);
            m_run[i] = m_new;
            float rs = 0.f;
#pragma unroll
            for (int j = 0; j < 4; j++) { s[i][j] = __expf(s[i][j] - m_new); rs += s[i][j]; }
#pragma unroll
            for (int o = 1; o < 16; o <<= 1) rs += __shfl_xor_sync(0xffffffffu, rs, o);
            l_run[i] = l_run[i] * alpha + rs;
#pragma unroll
            for (int j = 0; j < 4; j++) acc[i][j] *= alpha;
        }
        // store P transposed (col-major) for the PV stage
#pragma unroll
        for (int j = 0; j < 4; j++) {
            float4 pv; pv.x = s[0][j]; pv.y = s[1][j]; pv.z = s[2][j]; pv.w = s[3][j];
            *(float4*)(&sPT[(tx * 4 + j) * 68 + ty * 4]) = pv;
        }
        __syncthreads();
        // PV accumulate
#pragma unroll 8
        for (int kk = 0; kk < 64; kk++) {
            float4 a4 = *(float4*)(&sPT[kk * 68 + ty * 4]);
            float4 b4 = *(float4*)(&sV[kk * 68 + tx * 4]);
            float a[4] = {a4.x, a4.y, a4.z, a4.w};
            float bb[4] = {b4.x, b4.y, b4.z, b4.w};
#pragma unroll
            for (int i = 0; i < 4; i++)
#pragma unroll
                for (int j = 0; j < 4; j++) acc[i][j] += a[i] * bb[j];
        }
    }
    // write O[b, q, h*64 + c]  (bqhd layout)
#pragma unroll
    for (int i = 0; i < 4; i++) {
        float inv = 1.f / l_run[i];
        int qrow = q0 + ty * 4 + i;
        float4 c;
        c.x = acc[i][0] * inv; c.y = acc[i][1] * inv;
        c.z = acc[i][2] * inv; c.w = acc[i][3] * inv;
        *(float4*)(O + ((size_t)(b * SS) + qrow) * D + h * DH + tx * 4) = c;
    }
}

// ---------------- LayerNorm over last dim (1024), one block per row ----------------
__global__ __launch_bounds__(256) void ln_kernel(
    const float* __restrict__ X, const float* __restrict__ g,
    const float* __restrict__ be, float* __restrict__ Y)
{
    __shared__ float ss[8], ssq[8];
    int row = blockIdx.x;
    int tid = threadIdx.x;
    const float* x = X + (size_t)row * D;
    float4 v = ((const float4*)x)[tid];
    float s = v.x + v.y + v.z + v.w;
    float sq = v.x * v.x + v.y * v.y + v.z * v.z + v.w * v.w;
#pragma unroll
    for (int o = 16; o; o >>= 1) {
        s += __shfl_xor_sync(0xffffffffu, s, o);
        sq += __shfl_xor_sync(0xffffffffu, sq, o);
    }
    int w = tid >> 5;
    if ((tid & 31) == 0) { ss[w] = s; ssq[w] = sq; }
    __syncthreads();
    if (tid < 32) {
        s = (tid < 8) ? ss[tid] : 0.f;
        sq = (tid < 8) ? ssq[tid] : 0.f;
#pragma unroll
        for (int o = 4; o; o >>= 1) {
            s += __shfl_xor_sync(0xffffffffu, s, o);
            sq += __shfl_xor_sync(0xffffffffu, sq, o);
        }
        if (tid == 0) { ss[0] = s; ssq[0] = sq; }
    }
    __syncthreads();
    float mean = ss[0] * (1.f / D);
    float var = ssq[0] * (1.f / D) - mean * mean;
    float inv = rsqrtf(var + 1e-6f);
    float4 gg = ((const float4*)g)[tid];
    float4 bb = ((const float4*)be)[tid];
    float4 o;
    o.x = (v.x - mean) * inv * gg.x + bb.x;
    o.y = (v.y - mean) * inv * gg.y + bb.y;
    o.z = (v.z - mean) * inv * gg.z + bb.z;
    o.w = (v.w - mean) * inv * gg.w + bb.w;
    ((float4*)(Y + (size_t)row * D))[tid] = o;
}

// ---------------- host orchestration ----------------
extern "C" void kernel_launch(void* const* d_in, const int* in_sizes, int n_in,
                              void* d_out, int out_size)
{
    const float* x_in = (const float*)d_in[0];
    const int*   rid  = (const int*)d_in[1];
    const float* Wq = (const float*)d_in[2];
    const float* bq = (const float*)d_in[3];
    const float* Wk = (const float*)d_in[4];
    const float* bk = (const float*)d_in[5];
    const float* Wv = (const float*)d_in[6];
    const float* bv = (const float*)d_in[7];
    const float* Wo = (const float*)d_in[8];
    const float* bo = (const float*)d_in[9];
    const float* Erel = (const float*)d_in[10];
    const float* Brel = (const float*)d_in[11];
    const float* g1  = (const float*)d_in[12];
    const float* be1 = (const float*)d_in[13];
    const float* g2  = (const float*)d_in[14];
    const float* be2 = (const float*)d_in[15];
    const float* W1 = (const float*)d_in[16];
    const float* b1 = (const float*)d_in[17];
    const float* W2 = (const float*)d_in[18];
    const float* b2 = (const float*)d_in[19];

    float *q, *k, *v, *a, *t, *ffin, *xg, *hh, *qe;
    cudaGetSymbolAddress((void**)&q, g_q);
    cudaGetSymbolAddress((void**)&k, g_k);
    cudaGetSymbolAddress((void**)&v, g_v);
    cudaGetSymbolAddress((void**)&a, g_a);
    cudaGetSymbolAddress((void**)&t, g_t);
    cudaGetSymbolAddress((void**)&ffin, g_ffin);
    cudaGetSymbolAddress((void**)&xg, g_x);
    cudaGetSymbolAddress((void**)&hh, g_h);
    cudaGetSymbolAddress((void**)&qe, g_qE);

    size_t att_smem = (size_t)ATT_SMEM_FLOATS * sizeof(float);
    cudaFuncSetAttribute(attn_kernel, cudaFuncAttributeMaxDynamicSharedMemorySize, (int)att_smem);

    const float* X = x_in;
    for (int l = 0; l < NL; l++) {
        const size_t wDD = (size_t)l * D * D;
        // fused QKV: one launch, z selects {q,k,v}
        gemm_tc<<<dim3(8, 32, 3), 256>>>(X,
            Wq + wDD, Wk + wDD, Wv + wDD,
            bq + l * D, bk + l * D, bv + l * D,
            nullptr, q, k, v, BS, D, D, 0);
        qe_kernel<<<BS, 256>>>(q, Erel + (size_t)l * NB * DH, qe);
        attn_kernel<<<dim3(16, 16, 4), 256, att_smem>>>(q, k, v, qe, Brel + (size_t)l * H * NB, rid, a);
        gemm_tc<<<dim3(8, 32, 1), 256>>>(a, Wo + wDD, nullptr, nullptr,
            bo + l * D, nullptr, nullptr, X, t, nullptr, nullptr, BS, D, D, 0);
        ln_kernel<<<BS, 256>>>(t, g1 + l * D, be1 + l * D, ffin);
        gemm_tc<<<dim3(32, 32, 1), 256>>>(ffin, W1 + (size_t)l * D * FF, nullptr, nullptr,
            b1 + (size_t)l * FF, nullptr, nullptr, nullptr, hh, nullptr, nullptr, BS, FF, D, 1);
        gemm_tc<<<dim3(8, 32, 1), 256>>>(hh, W2 + (size_t)l * FF * D, nullptr, nullptr,
            b2 + l * D, nullptr, nullptr, ffin, t, nullptr, nullptr, BS, D, FF, 0);
        float* out = (l == NL - 1) ? (float*)d_out : xg;
        ln_kernel<<<BS, 256>>>(t, g2 + l * D, be2 + l * D, out);
        X = xg;
    }
}

// round 7
// speedup vs baseline: 1.9154x; 1.0472x over previous
#include <cuda_runtime.h>
#include <cuda_bf16.h>
#include <cstdint>
#include <cstddef>

#define NL 6
#define D 1024
#define H 16
#define FF 4096
#define NB 33
#define DH 64
#define BB 4
#define SS 1024
#define BS (BB*SS)   // 4096

// ---------------- fp32 scratch ----------------
__device__ float g_q[BS*D];
__device__ float g_k[BS*D];
__device__ float g_v[BS*D];
__device__ float g_t[BS*D];
__device__ float g_ffin[BS*D];
__device__ float g_x[BS*D];
__device__ float g_qE[(size_t)BB*H*SS*NB];

// ---------------- bf16 hi/lo plane scratch ----------------
__device__ __nv_bfloat16 g_wqh[NL*D*D], g_wql[NL*D*D];
__device__ __nv_bfloat16 g_wkh[NL*D*D], g_wkl[NL*D*D];
__device__ __nv_bfloat16 g_wvh[NL*D*D], g_wvl[NL*D*D];
__device__ __nv_bfloat16 g_woh[NL*D*D], g_wol[NL*D*D];
__device__ __nv_bfloat16 g_w1h[(size_t)NL*D*FF], g_w1l[(size_t)NL*D*FF];
__device__ __nv_bfloat16 g_w2h[(size_t)NL*FF*D], g_w2l[(size_t)NL*FF*D];
__device__ __nv_bfloat16 g_xh[BS*D], g_xl[BS*D];       // layer input planes
__device__ __nv_bfloat16 g_ah[BS*D], g_al[BS*D];       // attention output planes
__device__ __nv_bfloat16 g_fh[BS*D], g_fl[BS*D];       // ffin planes
__device__ __nv_bfloat16 g_hh[(size_t)BS*FF], g_hl[(size_t)BS*FF];  // ffn hidden planes

// ---------------- helpers ----------------
__device__ __forceinline__ uint32_t smem_u32(const void* p) {
    return (uint32_t)__cvta_generic_to_shared(p);
}
__device__ __forceinline__ uint32_t pack_hi2(float a, float b) {
    __nv_bfloat162 t = __floats2bfloat162_rn(a, b);
    return *reinterpret_cast<uint32_t*>(&t);
}
__device__ __forceinline__ uint32_t pack_lo2(float a, float b) {
    float ra = a - __bfloat162float(__float2bfloat16(a));
    float rb = b - __bfloat162float(__float2bfloat16(b));
    __nv_bfloat162 t = __floats2bfloat162_rn(ra, rb);
    return *reinterpret_cast<uint32_t*>(&t);
}
__device__ __forceinline__ void cpa16(void* dst, const void* src) {
    asm volatile("cp.async.cg.shared.global [%0], [%1], 16;"
                 :: "r"(smem_u32(dst)), "l"(src));
}
__device__ __forceinline__ void ldmx4(uint32_t* r, uint32_t addr) {
    asm volatile("ldmatrix.sync.aligned.m8n8.x4.shared.b16 {%0,%1,%2,%3}, [%4];"
                 : "=r"(r[0]), "=r"(r[1]), "=r"(r[2]), "=r"(r[3]) : "r"(addr));
}
__device__ __forceinline__ void ldmx2t(uint32_t* r, uint32_t addr) {
    asm volatile("ldmatrix.sync.aligned.m8n8.x2.trans.shared.b16 {%0,%1}, [%2];"
                 : "=r"(r[0]), "=r"(r[1]) : "r"(addr));
}
__device__ __forceinline__ void mma16816(float* c, const uint32_t* a, const uint32_t* b) {
    asm volatile("mma.sync.aligned.m16n8k16.row.col.f32.bf16.bf16.f32 "
                 "{%0,%1,%2,%3}, {%4,%5,%6,%7}, {%8,%9}, {%0,%1,%2,%3};"
                 : "+f"(c[0]), "+f"(c[1]), "+f"(c[2]), "+f"(c[3])
                 : "r"(a[0]), "r"(a[1]), "r"(a[2]), "r"(a[3]), "r"(b[0]), "r"(b[1]));
}

// ---------------- split fp32 -> bf16 hi/lo planes ----------------
__global__ __launch_bounds__(256) void split_kernel(
    const float* __restrict__ X, __nv_bfloat16* __restrict__ hi,
    __nv_bfloat16* __restrict__ lo, int n4)
{
    int i = blockIdx.x * 256 + threadIdx.x;
    if (i < n4) {
        float4 v = ((const float4*)X)[i];
        uint2 h, l;
        h.x = pack_hi2(v.x, v.y); h.y = pack_hi2(v.z, v.w);
        l.x = pack_lo2(v.x, v.y); l.y = pack_lo2(v.z, v.w);
        ((uint2*)hi)[i] = h;
        ((uint2*)lo)[i] = l;
    }
}

// ---------------- pure-bf16 split GEMM, cp.async double-buffered ----------------
// C = (Ah+Al)[MxK] @ (Bh+Bl)[KxN] (3-term) + bias (+res)(+relu); fp32 and/or plane out.
#define APAD 40
#define BPAD 136
#define AE (128*APAD)
#define BE (32*BPAD)
#define STAGE_E (2*AE + 2*BE)           // 18944 bf16
#define GEMM_SMEM (2*STAGE_E*2)         // bytes = 75776
__global__ __launch_bounds__(256) void gemm_bf(
    const __nv_bfloat16* __restrict__ Ah, const __nv_bfloat16* __restrict__ Al,
    const __nv_bfloat16* Bh0, const __nv_bfloat16* Bl0,
    const __nv_bfloat16* Bh1, const __nv_bfloat16* Bl1,
    const __nv_bfloat16* Bh2, const __nv_bfloat16* Bl2,
    const float* bias0, const float* bias1, const float* bias2,
    const float* __restrict__ res,
    float* C0, float* C1, float* C2,
    __nv_bfloat16* Ch, __nv_bfloat16* Cl,
    int M, int N, int K, int relu)
{
    extern __shared__ __nv_bfloat16 smem[];
    const __nv_bfloat16* Bph = (blockIdx.z == 0) ? Bh0 : (blockIdx.z == 1 ? Bh1 : Bh2);
    const __nv_bfloat16* Bpl = (blockIdx.z == 0) ? Bl0 : (blockIdx.z == 1 ? Bl1 : Bl2);
    const float* bias        = (blockIdx.z == 0) ? bias0 : (blockIdx.z == 1 ? bias1 : bias2);
    float* C                 = (blockIdx.z == 0) ? C0 : (blockIdx.z == 1 ? C1 : C2);

    int bm = blockIdx.y * 128, bn = blockIdx.x * 128;
    int tid = threadIdx.x;
    int lane = tid & 31, wid = tid >> 5;
    int wm = (wid >> 2) * 64, wn = (wid & 3) * 32;
    int nk = K >> 5;

    float acc[4][4][4];
#pragma unroll
    for (int i = 0; i < 4; i++)
#pragma unroll
        for (int j = 0; j < 4; j++)
#pragma unroll
            for (int t = 0; t < 4; t++) acc[i][j][t] = 0.f;

    // async stage loader: 8 cp.async of 16B per thread
    auto load_stage = [&](int kb, int s) {
        __nv_bfloat16* b = smem + s * STAGE_E;
        __nv_bfloat16* sAh = b, *sAl = b + AE, *sBh = b + 2*AE, *sBl = b + 2*AE + BE;
        int k0b = kb << 5;
#pragma unroll
        for (int u = 0; u < 2; u++) {
            int c = tid + u * 256;            // 0..511
            int ar = c >> 2, ac = (c & 3) << 3;
            size_t ga = (size_t)(bm + ar) * K + k0b + ac;
            cpa16(sAh + ar * APAD + ac, Ah + ga);
            cpa16(sAl + ar * APAD + ac, Al + ga);
            int br = c >> 4, bc = (c & 15) << 3;
            size_t gb = (size_t)(k0b + br) * N + bn + bc;
            cpa16(sBh + br * BPAD + bc, Bph + gb);
            cpa16(sBl + br * BPAD + bc, Bpl + gb);
        }
        asm volatile("cp.async.commit_group;");
    };

    load_stage(0, 0);
    for (int kb = 0; kb < nk; kb++) {
        if (kb + 1 < nk) {
            load_stage(kb + 1, (kb + 1) & 1);
            asm volatile("cp.async.wait_group 1;");
        } else {
            asm volatile("cp.async.wait_group 0;");
        }
        __syncthreads();

        __nv_bfloat16* b = smem + (kb & 1) * STAGE_E;
        __nv_bfloat16* sAh = b, *sAl = b + AE, *sBh = b + 2*AE, *sBl = b + 2*AE + BE;
#pragma unroll
        for (int h2 = 0; h2 < 2; h2++) {
            int k0 = h2 * 16;
            uint32_t bhf[4][2], blf[4][2];
            int brow = k0 + (lane & 15);
#pragma unroll
            for (int nj = 0; nj < 4; nj++) {
                ldmx2t(bhf[nj], smem_u32(&sBh[brow * BPAD + wn + nj * 8]));
                ldmx2t(blf[nj], smem_u32(&sBl[brow * BPAD + wn + nj * 8]));
            }
#pragma unroll
            for (int mi = 0; mi < 4; mi++) {
                int arow = wm + mi * 16 + (lane & 15);
                int acol = k0 + ((lane >> 4) << 3);
                uint32_t ahf[4], alf[4];
                ldmx4(ahf, smem_u32(&sAh[arow * APAD + acol]));
                ldmx4(alf, smem_u32(&sAl[arow * APAD + acol]));
#pragma unroll
                for (int nj = 0; nj < 4; nj++) {
                    mma16816(acc[mi][nj], ahf, bhf[nj]);   // hi*hi
                    mma16816(acc[mi][nj], ahf, blf[nj]);   // hi*lo
                    mma16816(acc[mi][nj], alf, bhf[nj]);   // lo*hi
                }
            }
        }
        __syncthreads();
    }

    // ---- epilogue ----
#pragma unroll
    for (int mi = 0; mi < 4; mi++) {
#pragma unroll
        for (int nj = 0; nj < 4; nj++) {
            int r0 = bm + wm + mi * 16 + (lane >> 2);
            int c0 = bn + wn + nj * 8 + (lane & 3) * 2;
#pragma unroll
            for (int half = 0; half < 2; half++) {
                int r = r0 + half * 8;
                float o0 = acc[mi][nj][half * 2 + 0] + bias[c0];
                float o1 = acc[mi][nj][half * 2 + 1] + bias[c0 + 1];
                if (res) {
                    float2 rr = *(const float2*)(res + (size_t)r * N + c0);
                    o0 += rr.x; o1 += rr.y;
                }
                if (relu) { o0 = fmaxf(o0, 0.f); o1 = fmaxf(o1, 0.f); }
                if (C) {
                    float2 o; o.x = o0; o.y = o1;
                    *(float2*)(C + (size_t)r * N + c0) = o;
                }
                if (Ch) {
                    *(uint32_t*)(Ch + (size_t)r * N + c0) = pack_hi2(o0, o1);
                    *(uint32_t*)(Cl + (size_t)r * N + c0) = pack_lo2(o0, o1);
                }
            }
        }
    }
}

// ---------------- qE[b,h,s,nb] = sum_d q[b,s,h*64+d] * Erel[nb,d] ----------------
__global__ __launch_bounds__(256) void qe_kernel(
    const float* __restrict__ Q, const float* __restrict__ Erel,
    float* __restrict__ qE)
{
    __shared__ float qrow[D];
    __shared__ float er[NB * DH];
    int bs = blockIdx.x;
    int b = bs >> 10, s = bs & 1023;
    for (int i = threadIdx.x; i < D / 4; i += 256)
        ((float4*)qrow)[i] = ((const float4*)(Q + (size_t)bs * D))[i];
    for (int i = threadIdx.x; i < NB * DH / 4; i += 256)
        ((float4*)er)[i] = ((const float4*)Erel)[i];
    __syncthreads();
    for (int idx = threadIdx.x; idx < H * NB; idx += 256) {
        int h = idx / NB, nb = idx % NB;
        float acc = 0.f;
#pragma unroll 16
        for (int d = 0; d < DH; d++) acc += qrow[h * DH + d] * er[nb * DH + d];
        qE[(((size_t)(b * H + h)) * SS + s) * NB + nb] = acc;
    }
}

// ---------------- flash attention; writes bf16 hi/lo plane output ----------------
#define ATT_SMEM_FLOATS (4*64*68 + 64*NB + 64)
__global__ __launch_bounds__(256) void attn_kernel(
    const float* __restrict__ Q, const float* __restrict__ Kg,
    const float* __restrict__ Vg, const float* __restrict__ qE,
    const float* __restrict__ Brel, const int* __restrict__ rid,
    __nv_bfloat16* __restrict__ Oh, __nv_bfloat16* __restrict__ Ol)
{
    extern __shared__ float sm[];
    float* sQT = sm;
    float* sKT = sQT + 64 * 68;
    float* sV  = sKT + 64 * 68;
    float* sPT = sV  + 64 * 68;
    float* sQE = sPT + 64 * 68;
    float* sB  = sQE + 64 * NB;

    int qb = blockIdx.x, h = blockIdx.y, b = blockIdx.z;
    int tid = threadIdx.x;
    int tx = tid & 15, ty = tid >> 4;
    int q0 = qb * 64;

    const float* Qb = Q + ((size_t)(b * SS) + q0) * D + h * DH;
    for (int i = tid; i < 64 * 16; i += 256) {
        int row = i >> 4;
        int c4 = (i & 15) << 2;
        float4 v = *(const float4*)(Qb + (size_t)row * D + c4);
        sQT[(c4 + 0) * 68 + row] = v.x; sQT[(c4 + 1) * 68 + row] = v.y;
        sQT[(c4 + 2) * 68 + row] = v.z; sQT[(c4 + 3) * 68 + row] = v.w;
    }
    const float* qEb = qE + (((size_t)(b * H + h)) * SS + q0) * NB;
    for (int i = tid; i < (64 * NB) / 4; i += 256)
        ((float4*)sQE)[i] = ((const float4*)qEb)[i];
    for (int i = tid; i < NB; i += 256) sB[i] = Brel[h * NB + i];

    float m_run[4], l_run[4], acc[4][4];
#pragma unroll
    for (int i = 0; i < 4; i++) {
        m_run[i] = -1e30f; l_run[i] = 0.f;
#pragma unroll
        for (int j = 0; j < 4; j++) acc[i][j] = 0.f;
    }

    for (int kb = 0; kb < 16; kb++) {
        __syncthreads();
        int k0 = kb * 64;
        const float* Kb = Kg + ((size_t)(b * SS) + k0) * D + h * DH;
        const float* Vb = Vg + ((size_t)(b * SS) + k0) * D + h * DH;
        for (int i = tid; i < 64 * 16; i += 256) {
            int row = i >> 4;
            int c4 = (i & 15) << 2;
            float4 v = *(const float4*)(Kb + (size_t)row * D + c4);
            sKT[(c4 + 0) * 68 + row] = v.x; sKT[(c4 + 1) * 68 + row] = v.y;
            sKT[(c4 + 2) * 68 + row] = v.z; sKT[(c4 + 3) * 68 + row] = v.w;
            float4 w = *(const float4*)(Vb + (size_t)row * D + c4);
            *(float4*)(&sV[row * 68 + c4]) = w;
        }
        __syncthreads();

        float s[4][4];
#pragma unroll
        for (int i = 0; i < 4; i++)
#pragma unroll
            for (int j = 0; j < 4; j++) s[i][j] = 0.f;
#pragma unroll 8
        for (int d = 0; d < 64; d++) {
            float4 a4 = *(float4*)(&sQT[d * 68 + ty * 4]);
            float4 b4 = *(float4*)(&sKT[d * 68 + tx * 4]);
            float a[4] = {a4.x, a4.y, a4.z, a4.w};
            float bb[4] = {b4.x, b4.y, b4.z, b4.w};
#pragma unroll
            for (int i = 0; i < 4; i++)
#pragma unroll
                for (int j = 0; j < 4; j++) s[i][j] += a[i] * bb[j];
        }
#pragma unroll
        for (int i = 0; i < 4; i++) {
            int qrow = ty * 4 + i;
            const int* rr = rid + (size_t)(q0 + qrow) * SS + k0 + tx * 4;
#pragma unroll
            for (int j = 0; j < 4; j++) {
                int id = rr[j];
                s[i][j] = (s[i][j] + sQE[qrow * NB + id] + sB[id]) * 0.125f;
            }
        }
#pragma unroll
        for (int i = 0; i < 4; i++) {
            float mx = fmaxf(fmaxf(s[i][0], s[i][1]), fmaxf(s[i][2], s[i][3]));
#pragma unroll
            for (int o = 1; o < 16; o <<= 1) mx = fmaxf(mx, __shfl_xor_sync(0xffffffffu, mx, o));
            float m_new = fmaxf(m_run[i], mx);
            float alpha = __expf(m_run[i] - m_new);
            m_run[i] = m_new;
            float rs = 0.f;
#pragma unroll
            for (int j = 0; j < 4; j++) { s[i][j] = __expf(s[i][j] - m_new); rs += s[i][j]; }
#pragma unroll
            for (int o = 1; o < 16; o <<= 1) rs += __shfl_xor_sync(0xffffffffu, rs, o);
            l_run[i] = l_run[i] * alpha + rs;
#pragma unroll
            for (int j = 0; j < 4; j++) acc[i][j] *= alpha;
        }
#pragma unroll
        for (int j = 0; j < 4; j++) {
            float4 pv; pv.x = s[0][j]; pv.y = s[1][j]; pv.z = s[2][j]; pv.w = s[3][j];
            *(float4*)(&sPT[(tx * 4 + j) * 68 + ty * 4]) = pv;
        }
        __syncthreads();
#pragma unroll 8
        for (int kk = 0; kk < 64; kk++) {
            float4 a4 = *(float4*)(&sPT[kk * 68 + ty * 4]);
            float4 b4 = *(float4*)(&sV[kk * 68 + tx * 4]);
            float a[4] = {a4.x, a4.y, a4.z, a4.w};
            float bb[4] = {b4.x, b4.y, b4.z, b4.w};
#pragma unroll
            for (int i = 0; i < 4; i++)
#pragma unroll
                for (int j = 0; j < 4; j++) acc[i][j] += a[i] * bb[j];
        }
    }
#pragma unroll
    for (int i = 0; i < 4; i++) {
        float inv = 1.f / l_run[i];
        int qrow = q0 + ty * 4 + i;
        float c0 = acc[i][0] * inv, c1 = acc[i][1] * inv;
        float c2 = acc[i][2] * inv, c3 = acc[i][3] * inv;
        size_t off = ((size_t)(b * SS) + qrow) * D + h * DH + tx * 4;
        uint2 hv, lv;
        hv.x = pack_hi2(c0, c1); hv.y = pack_hi2(c2, c3);
        lv.x = pack_lo2(c0, c1); lv.y = pack_lo2(c2, c3);
        *(uint2*)(Oh + off) = hv;
        *(uint2*)(Ol + off) = lv;
    }
}

// ---------------- LayerNorm; fp32 out + optional bf16 hi/lo planes ----------------
__global__ __launch_bounds__(256) void ln_kernel(
    const float* __restrict__ X, const float* __restrict__ g,
    const float* __restrict__ be, float* __restrict__ Y,
    __nv_bfloat16* __restrict__ Yh, __nv_bfloat16* __restrict__ Yl)
{
    __shared__ float ss[8], ssq[8];
    int row = blockIdx.x;
    int tid = threadIdx.x;
    const float* x = X + (size_t)row * D;
    float4 v = ((const float4*)x)[tid];
    float s = v.x + v.y + v.z + v.w;
    float sq = v.x * v.x + v.y * v.y + v.z * v.z + v.w * v.w;
#pragma unroll
    for (int o = 16; o; o >>= 1) {
        s += __shfl_xor_sync(0xffffffffu, s, o);
        sq += __shfl_xor_sync(0xffffffffu, sq, o);
    }
    int w = tid >> 5;
    if ((tid & 31) == 0) { ss[w] = s; ssq[w] = sq; }
    __syncthreads();
    if (tid < 32) {
        s = (tid < 8) ? ss[tid] : 0.f;
        sq = (tid < 8) ? ssq[tid] : 0.f;
#pragma unroll
        for (int o = 4; o; o >>= 1) {
            s += __shfl_xor_sync(0xffffffffu, s, o);
            sq += __shfl_xor_sync(0xffffffffu, sq, o);
        }
        if (tid == 0) { ss[0] = s; ssq[0] = sq; }
    }
    __syncthreads();
    float mean = ss[0] * (1.f / D);
    float var = ssq[0] * (1.f / D) - mean * mean;
    float inv = rsqrtf(var + 1e-6f);
    float4 gg = ((const float4*)g)[tid];
    float4 bb = ((const float4*)be)[tid];
    float4 o;
    o.x = (v.x - mean) * inv * gg.x + bb.x;
    o.y = (v.y - mean) * inv * gg.y + bb.y;
    o.z = (v.z - mean) * inv * gg.z + bb.z;
    o.w = (v.w - mean) * inv * gg.w + bb.w;
    ((float4*)(Y + (size_t)row * D))[tid] = o;
    if (Yh) {
        uint2 hv, lv;
        hv.x = pack_hi2(o.x, o.y); hv.y = pack_hi2(o.z, o.w);
        lv.x = pack_lo2(o.x, o.y); lv.y = pack_lo2(o.z, o.w);
        size_t off = (size_t)row * D + tid * 4;
        *(uint2*)(Yh + off) = hv;
        *(uint2*)(Yl + off) = lv;
    }
}

// ---------------- host orchestration ----------------
extern "C" void kernel_launch(void* const* d_in, const int* in_sizes, int n_in,
                              void* d_out, int out_size)
{
    const float* x_in = (const float*)d_in[0];
    const int*   rid  = (const int*)d_in[1];
    const float* Wq = (const float*)d_in[2];
    const float* bq = (const float*)d_in[3];
    const float* Wk = (const float*)d_in[4];
    const float* bk = (const float*)d_in[5];
    const float* Wv = (const float*)d_in[6];
    const float* bv = (const float*)d_in[7];
    const float* Wo = (const float*)d_in[8];
    const float* bo = (const float*)d_in[9];
    const float* Erel = (const float*)d_in[10];
    const float* Brel = (const float*)d_in[11];
    const float* g1  = (const float*)d_in[12];
    const float* be1 = (const float*)d_in[13];
    const float* g2  = (const float*)d_in[14];
    const float* be2 = (const float*)d_in[15];
    const float* W1 = (const float*)d_in[16];
    const float* b1 = (const float*)d_in[17];
    const float* W2 = (const float*)d_in[18];
    const float* b2 = (const float*)d_in[19];

    float *q, *k, *v, *t, *ffin, *xg, *qe;
    cudaGetSymbolAddress((void**)&q, g_q);
    cudaGetSymbolAddress((void**)&k, g_k);
    cudaGetSymbolAddress((void**)&v, g_v);
    cudaGetSymbolAddress((void**)&t, g_t);
    cudaGetSymbolAddress((void**)&ffin, g_ffin);
    cudaGetSymbolAddress((void**)&xg, g_x);
    cudaGetSymbolAddress((void**)&qe, g_qE);

    __nv_bfloat16 *wqh,*wql,*wkh,*wkl,*wvh,*wvl,*woh,*wol,*w1h,*w1l,*w2h,*w2l;
    __nv_bfloat16 *xh,*xl,*ah,*al,*fh,*fl,*hh,*hl;
    cudaGetSymbolAddress((void**)&wqh, g_wqh); cudaGetSymbolAddress((void**)&wql, g_wql);
    cudaGetSymbolAddress((void**)&wkh, g_wkh); cudaGetSymbolAddress((void**)&wkl, g_wkl);
    cudaGetSymbolAddress((void**)&wvh, g_wvh); cudaGetSymbolAddress((void**)&wvl, g_wvl);
    cudaGetSymbolAddress((void**)&woh, g_woh); cudaGetSymbolAddress((void**)&wol, g_wol);
    cudaGetSymbolAddress((void**)&w1h, g_w1h); cudaGetSymbolAddress((void**)&w1l, g_w1l);
    cudaGetSymbolAddress((void**)&w2h, g_w2h); cudaGetSymbolAddress((void**)&w2l, g_w2l);
    cudaGetSymbolAddress((void**)&xh, g_xh);   cudaGetSymbolAddress((void**)&xl, g_xl);
    cudaGetSymbolAddress((void**)&ah, g_ah);   cudaGetSymbolAddress((void**)&al, g_al);
    cudaGetSymbolAddress((void**)&fh, g_fh);   cudaGetSymbolAddress((void**)&fl, g_fl);
    cudaGetSymbolAddress((void**)&hh, g_hh);   cudaGetSymbolAddress((void**)&hl, g_hl);

    cudaFuncSetAttribute(gemm_bf, cudaFuncAttributeMaxDynamicSharedMemorySize, GEMM_SMEM);
    size_t att_smem = (size_t)ATT_SMEM_FLOATS * sizeof(float);
    cudaFuncSetAttribute(attn_kernel, cudaFuncAttributeMaxDynamicSharedMemorySize, (int)att_smem);

    // ---- pre-split weights (constant per launch) and layer-0 input ----
    {
        int nDD = NL * D * D / 4;                 // 1572864
        int nDF = (int)((size_t)NL * D * FF / 4); // 6291456
        int nX  = BS * D / 4;                     // 1048576
        split_kernel<<<(nDD + 255) / 256, 256>>>(Wq, wqh, wql, nDD);
        split_kernel<<<(nDD + 255) / 256, 256>>>(Wk, wkh, wkl, nDD);
        split_kernel<<<(nDD + 255) / 256, 256>>>(Wv, wvh, wvl, nDD);
        split_kernel<<<(nDD + 255) / 256, 256>>>(Wo, woh, wol, nDD);
        split_kernel<<<(nDF + 255) / 256, 256>>>(W1, w1h, w1l, nDF);
        split_kernel<<<(nDF + 255) / 256, 256>>>(W2, w2h, w2l, nDF);
        split_kernel<<<(nX + 255) / 256, 256>>>(x_in, xh, xl, nX);
    }

    const float* Xf = x_in;
    for (int l = 0; l < NL; l++) {
        const size_t wDD = (size_t)l * D * D;
        const size_t wDF = (size_t)l * D * FF;
        // fused QKV
        gemm_bf<<<dim3(8, 32, 3), 256, GEMM_SMEM>>>(xh, xl,
            wqh + wDD, wql + wDD, wkh + wDD, wkl + wDD, wvh + wDD, wvl + wDD,
            bq + l * D, bk + l * D, bv + l * D, nullptr,
            q, k, v, nullptr, nullptr, BS, D, D, 0);
        qe_kernel<<<BS, 256>>>(q, Erel + (size_t)l * NB * DH, qe);
        attn_kernel<<<dim3(16, 16, 4), 256, att_smem>>>(q, k, v, qe,
            Brel + (size_t)l * H * NB, rid, ah, al);
        // Wo + residual
        gemm_bf<<<dim3(8, 32, 1), 256, GEMM_SMEM>>>(ah, al,
            woh + wDD, wol + wDD, nullptr, nullptr, nullptr, nullptr,
            bo + l * D, nullptr, nullptr, Xf,
            t, nullptr, nullptr, nullptr, nullptr, BS, D, D, 0);
        ln_kernel<<<BS, 256>>>(t, g1 + l * D, be1 + l * D, ffin, fh, fl);
        // W1 + relu -> planes only
        gemm_bf<<<dim3(32, 32, 1), 256, GEMM_SMEM>>>(fh, fl,
            w1h + wDF, w1l + wDF, nullptr, nullptr, nullptr, nullptr,
            b1 + (size_t)l * FF, nullptr, nullptr, nullptr,
            nullptr, nullptr, nullptr, hh, hl, BS, FF, D, 1);
        // W2 + residual
        gemm_bf<<<dim3(8, 32, 1), 256, GEMM_SMEM>>>(hh, hl,
            w2h + wDF, w2l + wDF, nullptr, nullptr, nullptr, nullptr,
            b2 + l * D, nullptr, nullptr, ffin,
            t, nullptr, nullptr, nullptr, nullptr, BS, D, FF, 0);
        float* out = (l == NL - 1) ? (float*)d_out : xg;
        __nv_bfloat16* oh = (l == NL - 1) ? nullptr : xh;
        __nv_bfloat16* ol = (l == NL - 1) ? nullptr : xl;
        ln_kernel<<<BS, 256>>>(t, g2 + l * D, be2 + l * D, out, oh, ol);
        Xf = xg;
    }
}

// round 12
// speedup vs baseline: 2.4747x; 1.2921x over previous
#include <cuda_runtime.h>
#include <cuda_bf16.h>
#include <cstdint>
#include <cstddef>

#define NL 6
#define D 1024
#define H 16
#define FF 4096
#define NB 33
#define DH 64
#define BB 4
#define SS 1024
#define BS (BB*SS)   // 4096

typedef __nv_bfloat16 bf16;

// ---------------- fp32 scratch ----------------
__device__ float g_q[BS*D];
__device__ float g_t[BS*D];
__device__ float g_ffin[BS*D];
__device__ float g_x[BS*D];
__device__ float g_qE[(size_t)BB*H*SS*NB];

// ---------------- bf16 hi/lo plane scratch (weights [K][N] layout, round-7 proven) ----------------
__device__ bf16 g_wqh[NL*D*D], g_wql[NL*D*D];
__device__ bf16 g_wkh[NL*D*D], g_wkl[NL*D*D];
__device__ bf16 g_wvh[NL*D*D], g_wvl[NL*D*D];
__device__ bf16 g_woh[NL*D*D], g_wol[NL*D*D];
__device__ bf16 g_w1h[(size_t)NL*D*FF], g_w1l[(size_t)NL*D*FF];
__device__ bf16 g_w2h[(size_t)NL*FF*D], g_w2l[(size_t)NL*FF*D];
__device__ bf16 g_xh[BS*D], g_xl[BS*D];
__device__ bf16 g_qph[BS*D], g_qpl[BS*D];   // q planes
__device__ bf16 g_kph[BS*D], g_kpl[BS*D];   // k planes
__device__ bf16 g_vph[BS*D], g_vpl[BS*D];   // v planes
__device__ bf16 g_ah[BS*D], g_al[BS*D];
__device__ bf16 g_fh[BS*D], g_fl[BS*D];
__device__ bf16 g_hh[(size_t)BS*FF], g_hl[(size_t)BS*FF];

// ---------------- helpers ----------------
__device__ __forceinline__ uint32_t smem_u32(const void* p) {
    return (uint32_t)__cvta_generic_to_shared(p);
}
__device__ __forceinline__ uint32_t pack_hi2(float a, float b) {
    __nv_bfloat162 t = __floats2bfloat162_rn(a, b);
    return *reinterpret_cast<uint32_t*>(&t);
}
__device__ __forceinline__ uint32_t pack_lo2(float a, float b) {
    float ra = a - __bfloat162float(__float2bfloat16(a));
    float rb = b - __bfloat162float(__float2bfloat16(b));
    __nv_bfloat162 t = __floats2bfloat162_rn(ra, rb);
    return *reinterpret_cast<uint32_t*>(&t);
}
__device__ __forceinline__ void cpa16(uint32_t dst_smem, const void* src) {
    asm volatile("cp.async.cg.shared.global [%0], [%1], 16;"
                 :: "r"(dst_smem), "l"(src));
}
__device__ __forceinline__ void ldmx4(uint32_t* r, uint32_t addr) {
    asm volatile("ldmatrix.sync.aligned.m8n8.x4.shared.b16 {%0,%1,%2,%3}, [%4];"
                 : "=r"(r[0]), "=r"(r[1]), "=r"(r[2]), "=r"(r[3]) : "r"(addr));
}
__device__ __forceinline__ void ldmx2t(uint32_t* r, uint32_t addr) {
    asm volatile("ldmatrix.sync.aligned.m8n8.x2.trans.shared.b16 {%0,%1}, [%2];"
                 : "=r"(r[0]), "=r"(r[1]) : "r"(addr));
}
__device__ __forceinline__ void ldmx2(uint32_t* r, uint32_t addr) {
    asm volatile("ldmatrix.sync.aligned.m8n8.x2.shared.b16 {%0,%1}, [%2];"
                 : "=r"(r[0]), "=r"(r[1]) : "r"(addr));
}
__device__ __forceinline__ void mma16816(float* c, const uint32_t* a, const uint32_t* b) {
    asm volatile("mma.sync.aligned.m16n8k16.row.col.f32.bf16.bf16.f32 "
                 "{%0,%1,%2,%3}, {%4,%5,%6,%7}, {%8,%9}, {%0,%1,%2,%3};"
                 : "+f"(c[0]), "+f"(c[1]), "+f"(c[2]), "+f"(c[3])
                 : "r"(a[0]), "r"(a[1]), "r"(a[2]), "r"(a[3]), "r"(b[0]), "r"(b[1]));
}

// ---------------- split fp32 -> bf16 hi/lo planes ----------------
__global__ __launch_bounds__(256) void split_kernel(
    const float* __restrict__ X, bf16* __restrict__ hi, bf16* __restrict__ lo, int n4)
{
    int i = blockIdx.x * 256 + threadIdx.x;
    if (i < n4) {
        float4 v = ((const float4*)X)[i];
        uint2 h, l;
        h.x = pack_hi2(v.x, v.y); h.y = pack_hi2(v.z, v.w);
        l.x = pack_lo2(v.x, v.y); l.y = pack_lo2(v.z, v.w);
        ((uint2*)hi)[i] = h;
        ((uint2*)lo)[i] = l;
    }
}

// ---------------- pure-bf16 split GEMM (round-7 proven), cp.async double-buffered ----------------
#define APAD 40
#define BPAD 136
#define AE (128*APAD)
#define BE (32*BPAD)
#define STAGE_E (2*AE + 2*BE)
#define GEMM_SMEM (2*STAGE_E*2)
__global__ __launch_bounds__(256) void gemm_bf(
    const bf16* __restrict__ Ah, const bf16* __restrict__ Al,
    const bf16* Bh0, const bf16* Bl0, const bf16* Bh1, const bf16* Bl1,
    const bf16* Bh2, const bf16* Bl2,
    const float* bias0, const float* bias1, const float* bias2,
    const float* __restrict__ res,
    float* C0, float* C1, float* C2,
    bf16* Ch0, bf16* Cl0, bf16* Ch1, bf16* Cl1, bf16* Ch2, bf16* Cl2,
    int M, int N, int K, int relu)
{
    extern __shared__ bf16 smem[];
    const bf16* Bph = (blockIdx.z == 0) ? Bh0 : (blockIdx.z == 1 ? Bh1 : Bh2);
    const bf16* Bpl = (blockIdx.z == 0) ? Bl0 : (blockIdx.z == 1 ? Bl1 : Bl2);
    const float* bias = (blockIdx.z == 0) ? bias0 : (blockIdx.z == 1 ? bias1 : bias2);
    float* C = (blockIdx.z == 0) ? C0 : (blockIdx.z == 1 ? C1 : C2);
    bf16* Ch = (blockIdx.z == 0) ? Ch0 : (blockIdx.z == 1 ? Ch1 : Ch2);
    bf16* Cl = (blockIdx.z == 0) ? Cl0 : (blockIdx.z == 1 ? Cl1 : Cl2);

    int bm = blockIdx.y * 128, bn = blockIdx.x * 128;
    int tid = threadIdx.x;
    int lane = tid & 31, wid = tid >> 5;
    int wm = (wid >> 2) * 64, wn = (wid & 3) * 32;
    int nk = K >> 5;

    float acc[4][4][4];
#pragma unroll
    for (int i = 0; i < 4; i++)
#pragma unroll
        for (int j = 0; j < 4; j++)
#pragma unroll
            for (int t = 0; t < 4; t++) acc[i][j][t] = 0.f;

    auto load_stage = [&](int kb, int s) {
        bf16* b = smem + s * STAGE_E;
        bf16* sAh = b; bf16* sAl = b + AE; bf16* sBh = b + 2*AE; bf16* sBl = b + 2*AE + BE;
        int k0b = kb << 5;
#pragma unroll
        for (int u = 0; u < 2; u++) {
            int c = tid + u * 256;
            int ar = c >> 2, ac = (c & 3) << 3;
            size_t ga = (size_t)(bm + ar) * K + k0b + ac;
            cpa16(smem_u32(sAh + ar * APAD + ac), Ah + ga);
            cpa16(smem_u32(sAl + ar * APAD + ac), Al + ga);
            int br = c >> 4, bc = (c & 15) << 3;
            size_t gb = (size_t)(k0b + br) * N + bn + bc;
            cpa16(smem_u32(sBh + br * BPAD + bc), Bph + gb);
            cpa16(smem_u32(sBl + br * BPAD + bc), Bpl + gb);
        }
        asm volatile("cp.async.commit_group;");
    };

    load_stage(0, 0);
    for (int kb = 0; kb < nk; kb++) {
        if (kb + 1 < nk) {
            load_stage(kb + 1, (kb + 1) & 1);
            asm volatile("cp.async.wait_group 1;");
        } else {
            asm volatile("cp.async.wait_group 0;");
        }
        __syncthreads();

        bf16* b = smem + (kb & 1) * STAGE_E;
        bf16* sAh = b; bf16* sAl = b + AE; bf16* sBh = b + 2*AE; bf16* sBl = b + 2*AE + BE;
#pragma unroll
        for (int h2 = 0; h2 < 2; h2++) {
            int k0 = h2 * 16;
            uint32_t bhf[4][2], blf[4][2];
            int brow = k0 + (lane & 15);
#pragma unroll
            for (int nj = 0; nj < 4; nj++) {
                ldmx2t(bhf[nj], smem_u32(&sBh[brow * BPAD + wn + nj * 8]));
                ldmx2t(blf[nj], smem_u32(&sBl[brow * BPAD + wn + nj * 8]));
            }
#pragma unroll
            for (int mi = 0; mi < 4; mi++) {
                int arow = wm + mi * 16 + (lane & 15);
                int acol = k0 + ((lane >> 4) << 3);
                uint32_t ahf[4], alf[4];
                ldmx4(ahf, smem_u32(&sAh[arow * APAD + acol]));
                ldmx4(alf, smem_u32(&sAl[arow * APAD + acol]));
#pragma unroll
                for (int nj = 0; nj < 4; nj++) {
                    mma16816(acc[mi][nj], ahf, bhf[nj]);
                    mma16816(acc[mi][nj], ahf, blf[nj]);
                    mma16816(acc[mi][nj], alf, bhf[nj]);
                }
            }
        }
        __syncthreads();
    }

#pragma unroll
    for (int mi = 0; mi < 4; mi++) {
#pragma unroll
        for (int nj = 0; nj < 4; nj++) {
            int r0 = bm + wm + mi * 16 + (lane >> 2);
            int c0 = bn + wn + nj * 8 + (lane & 3) * 2;
#pragma unroll
            for (int half = 0; half < 2; half++) {
                int r = r0 + half * 8;
                float o0 = acc[mi][nj][half * 2 + 0] + bias[c0];
                float o1 = acc[mi][nj][half * 2 + 1] + bias[c0 + 1];
                if (res) {
                    float2 rr = *(const float2*)(res + (size_t)r * N + c0);
                    o0 += rr.x; o1 += rr.y;
                }
                if (relu) { o0 = fmaxf(o0, 0.f); o1 = fmaxf(o1, 0.f); }
                if (C) {
                    float2 o; o.x = o0; o.y = o1;
                    *(float2*)(C + (size_t)r * N + c0) = o;
                }
                if (Ch) {
                    *(uint32_t*)(Ch + (size_t)r * N + c0) = pack_hi2(o0, o1);
                    *(uint32_t*)(Cl + (size_t)r * N + c0) = pack_lo2(o0, o1);
                }
            }
        }
    }
}

// ---------------- qE[b,h,s,nb] = sum_d q[b,s,h*64+d] * Erel[nb,d] ----------------
__global__ __launch_bounds__(256) void qe_kernel(
    const float* __restrict__ Q, const float* __restrict__ Erel, float* __restrict__ qE)
{
    __shared__ float qrow[D];
    __shared__ float er[NB * DH];
    int bs = blockIdx.x;
    int b = bs >> 10, s = bs & 1023;
    for (int i = threadIdx.x; i < D / 4; i += 256)
        ((float4*)qrow)[i] = ((const float4*)(Q + (size_t)bs * D))[i];
    for (int i = threadIdx.x; i < NB * DH / 4; i += 256)
        ((float4*)er)[i] = ((const float4*)Erel)[i];
    __syncthreads();
    for (int idx = threadIdx.x; idx < H * NB; idx += 256) {
        int h = idx / NB, nb = idx % NB;
        float acc = 0.f;
#pragma unroll 16
        for (int d = 0; d < DH; d++) acc += qrow[h * DH + d] * er[nb * DH + d];
        qE[(((size_t)(b * H + h)) * SS + s) * NB + nb] = acc;
    }
}

// ---------------- tensor-core flash attention (split-bf16 mma) ----------------
// 64q x head x batch per block; 8 warps = 4 q-strips x 2 kk-halves.
// Smem bytes: Qh 0, Ql 9216, Kh 18432, Kl 27648, Vh 36864, Vl 46080,
//             QE 55296 (64x34 f32), Br 64000, Red 64144 (2x64 f32). Total 64656.
// Merge buffer aliases Kh/Kl (f32 [64][72] = 18432B).
#define ATT_SMEM 64656
__global__ __launch_bounds__(256) void attn_mma(
    const bf16* __restrict__ qh, const bf16* __restrict__ ql,
    const bf16* __restrict__ kh, const bf16* __restrict__ kl,
    const bf16* __restrict__ vh, const bf16* __restrict__ vl,
    const float* __restrict__ qE, const float* __restrict__ Brel,
    const int* __restrict__ rid,
    bf16* __restrict__ Oh, bf16* __restrict__ Ol)
{
    extern __shared__ char smc[];
    float* sQE = (float*)(smc + 55296);
    float* sBr = (float*)(smc + 64000);
    float* sRed = (float*)(smc + 64144);
    float* sMrg = (float*)(smc + 18432);   // alias K planes (dead after loop)
    uint32_t sb = smem_u32(smc);

    int qb = blockIdx.x, h = blockIdx.y, b = blockIdx.z;
    int tid = threadIdx.x, lane = tid & 31, wid = tid >> 5;
    int wq = wid >> 1, wn = wid & 1;
    int qs = wq * 16, ns = wn * 32;
    int q0 = qb * 64;
    int rlo = lane >> 2;

    // load Q planes (plain 16B loads)
#pragma unroll
    for (int u = 0; u < 4; u++) {
        int f = tid + u * 256;
        int pl = f >> 9;
        int idx = f & 511; int r = idx >> 3, c = idx & 7;
        const bf16* src = pl ? ql : qh;
        uint4 vv = *(const uint4*)(src + ((size_t)(b * SS) + q0 + r) * D + h * DH + c * 8);
        *(uint4*)(smc + pl * 9216 + r * 144 + c * 16) = vv;
    }
    const float* qEb = qE + (((size_t)(b * H + h)) * SS + q0) * NB;
    for (int i = tid; i < 64 * NB; i += 256) {
        int r = i / NB, c = i - r * NB;
        sQE[r * 34 + c] = qEb[r * NB + c];
    }
    for (int i = tid; i < NB; i += 256) sBr[i] = Brel[h * NB + i];

    float m_lo = -1e30f, m_hi = -1e30f, l_lo = 0.f, l_hi = 0.f;
    float oacc[8][4];
#pragma unroll
    for (int j = 0; j < 8; j++)
#pragma unroll
        for (int t = 0; t < 4; t++) oacc[j][t] = 0.f;

    for (int kb = 0; kb < 16; kb++) {
        __syncthreads();
        int k0 = kb * 64;
#pragma unroll
        for (int u = 0; u < 8; u++) {
            int f = tid + u * 256;
            int pl = f >> 9;                 // 0:Kh 1:Kl 2:Vh 3:Vl
            int idx = f & 511; int r = idx >> 3, c = idx & 7;
            const bf16* src = (pl == 0) ? kh : (pl == 1) ? kl : (pl == 2) ? vh : vl;
            cpa16(sb + 18432 + pl * 9216 + r * 144 + c * 16,
                  src + ((size_t)(b * SS) + k0 + r) * D + h * DH + c * 8);
        }
        asm volatile("cp.async.commit_group;");
        asm volatile("cp.async.wait_group 0;");
        __syncthreads();

        // ---- QK^T ----
        float sc[4][4];
#pragma unroll
        for (int j = 0; j < 4; j++)
#pragma unroll
            for (int t = 0; t < 4; t++) sc[j][t] = 0.f;
#pragma unroll
        for (int ks = 0; ks < 4; ks++) {
            uint32_t arow = qs + (lane & 15);
            uint32_t acol = (ks * 16 + ((lane >> 4) << 3)) * 2;
            uint32_t aQh[4], aQl[4];
            ldmx4(aQh, sb + arow * 144 + acol);
            ldmx4(aQl, sb + 9216 + arow * 144 + acol);
            int Lr = lane & 15;
            uint32_t bro = (ns + (Lr & 7)) * 144 + (ks * 16 + ((Lr >> 3) << 3)) * 2;
#pragma unroll
            for (int nj = 0; nj < 4; nj++) {
                uint32_t bh_[2], bl_[2];
                ldmx2(bh_, sb + 18432 + bro + nj * 8 * 144);
                ldmx2(bl_, sb + 27648 + bro + nj * 8 * 144);
                mma16816(sc[nj], aQh, bh_);
                mma16816(sc[nj], aQh, bl_);
                mma16816(sc[nj], aQl, bh_);
            }
        }
        // ---- gathers + scale ----
        int qlo = qs + rlo, qhi = qlo + 8;
#pragma unroll
        for (int nj = 0; nj < 4; nj++) {
            int kkl = ns + nj * 8 + (lane & 3) * 2;
            int2 r1 = *(const int2*)(rid + (size_t)(q0 + qlo) * SS + k0 + kkl);
            int2 r2 = *(const int2*)(rid + (size_t)(q0 + qhi) * SS + k0 + kkl);
            sc[nj][0] = (sc[nj][0] + sQE[qlo * 34 + r1.x] + sBr[r1.x]) * 0.125f;
            sc[nj][1] = (sc[nj][1] + sQE[qlo * 34 + r1.y] + sBr[r1.y]) * 0.125f;
            sc[nj][2] = (sc[nj][2] + sQE[qhi * 34 + r2.x] + sBr[r2.x]) * 0.125f;
            sc[nj][3] = (sc[nj][3] + sQE[qhi * 34 + r2.y] + sBr[r2.y]) * 0.125f;
        }
        // ---- row max (4-lane group, then cross n-warp via smem) ----
        float mxlo = fmaxf(fmaxf(sc[0][0], sc[0][1]), fmaxf(sc[1][0], sc[1][1]));
        mxlo = fmaxf(mxlo, fmaxf(fmaxf(sc[2][0], sc[2][1]), fmaxf(sc[3][0], sc[3][1])));
        float mxhi = fmaxf(fmaxf(sc[0][2], sc[0][3]), fmaxf(sc[1][2], sc[1][3]));
        mxhi = fmaxf(mxhi, fmaxf(fmaxf(sc[2][2], sc[2][3]), fmaxf(sc[3][2], sc[3][3])));
#pragma unroll
        for (int o = 1; o < 4; o <<= 1) {
            mxlo = fmaxf(mxlo, __shfl_xor_sync(0xffffffffu, mxlo, o));
            mxhi = fmaxf(mxhi, __shfl_xor_sync(0xffffffffu, mxhi, o));
        }
        if ((lane & 3) == 0) {
            sRed[wn * 64 + qlo] = mxlo;
            sRed[wn * 64 + qhi] = mxhi;
        }
        __syncthreads();
        float tlo = fmaxf(mxlo, sRed[(1 - wn) * 64 + qlo]);
        float thi = fmaxf(mxhi, sRed[(1 - wn) * 64 + qhi]);
        float mn_lo = fmaxf(m_lo, tlo), mn_hi = fmaxf(m_hi, thi);
        float al_lo = __expf(m_lo - mn_lo), al_hi = __expf(m_hi - mn_hi);
        m_lo = mn_lo; m_hi = mn_hi;
        float slo = 0.f, shi = 0.f;
#pragma unroll
        for (int nj = 0; nj < 4; nj++) {
            sc[nj][0] = __expf(sc[nj][0] - mn_lo);
            sc[nj][1] = __expf(sc[nj][1] - mn_lo);
            sc[nj][2] = __expf(sc[nj][2] - mn_hi);
            sc[nj][3] = __expf(sc[nj][3] - mn_hi);
            slo += sc[nj][0] + sc[nj][1];
            shi += sc[nj][2] + sc[nj][3];
        }
#pragma unroll
        for (int o = 1; o < 4; o <<= 1) {
            slo += __shfl_xor_sync(0xffffffffu, slo, o);
            shi += __shfl_xor_sync(0xffffffffu, shi, o);
        }
        l_lo = l_lo * al_lo + slo;
        l_hi = l_hi * al_hi + shi;
#pragma unroll
        for (int j = 0; j < 8; j++) {
            oacc[j][0] *= al_lo; oacc[j][1] *= al_lo;
            oacc[j][2] *= al_hi; oacc[j][3] *= al_hi;
        }
        // ---- P·V (P from registers as A fragments) ----
#pragma unroll
        for (int ks2 = 0; ks2 < 2; ks2++) {
            uint32_t aPh[4], aPl[4];
            aPh[0] = pack_hi2(sc[2 * ks2][0], sc[2 * ks2][1]);
            aPh[1] = pack_hi2(sc[2 * ks2][2], sc[2 * ks2][3]);
            aPh[2] = pack_hi2(sc[2 * ks2 + 1][0], sc[2 * ks2 + 1][1]);
            aPh[3] = pack_hi2(sc[2 * ks2 + 1][2], sc[2 * ks2 + 1][3]);
            aPl[0] = pack_lo2(sc[2 * ks2][0], sc[2 * ks2][1]);
            aPl[1] = pack_lo2(sc[2 * ks2][2], sc[2 * ks2][3]);
            aPl[2] = pack_lo2(sc[2 * ks2 + 1][0], sc[2 * ks2 + 1][1]);
            aPl[3] = pack_lo2(sc[2 * ks2 + 1][2], sc[2 * ks2 + 1][3]);
            uint32_t bro = (ns + ks2 * 16 + (lane & 15)) * 144;
#pragma unroll
            for (int njd = 0; njd < 8; njd++) {
                uint32_t bh_[2], bl_[2];
                ldmx2t(bh_, sb + 36864 + bro + njd * 16);
                ldmx2t(bl_, sb + 46080 + bro + njd * 16);
                mma16816(oacc[njd], aPh, bh_);
                mma16816(oacc[njd], aPh, bl_);
                mma16816(oacc[njd], aPl, bh_);
            }
        }
    }
    // ---- merge the two kk-half partials + write planes ----
    __syncthreads();
    int qlo = qs + rlo, qhi = qlo + 8;
    if (wn == 1) {
#pragma unroll
        for (int njd = 0; njd < 8; njd++) {
            int col = njd * 8 + (lane & 3) * 2;
            float2 a1; a1.x = oacc[njd][0]; a1.y = oacc[njd][1];
            float2 a2; a2.x = oacc[njd][2]; a2.y = oacc[njd][3];
            *(float2*)&sMrg[qlo * 72 + col] = a1;
            *(float2*)&sMrg[qhi * 72 + col] = a2;
        }
        if ((lane & 3) == 0) { sRed[64 + qlo] = l_lo; sRed[64 + qhi] = l_hi; }
    }
    __syncthreads();
    if (wn == 0) {
        float iv_lo = 1.f / (l_lo + sRed[64 + qlo]);
        float iv_hi = 1.f / (l_hi + sRed[64 + qhi]);
        int qglo = q0 + qlo, qghi = q0 + qhi;
#pragma unroll
        for (int njd = 0; njd < 8; njd++) {
            int col = njd * 8 + (lane & 3) * 2;
            float2 x1 = *(float2*)&sMrg[qlo * 72 + col];
            float2 x2 = *(float2*)&sMrg[qhi * 72 + col];
            float o0 = (oacc[njd][0] + x1.x) * iv_lo;
            float o1 = (oacc[njd][1] + x1.y) * iv_lo;
            float o2 = (oacc[njd][2] + x2.x) * iv_hi;
            float o3 = (oacc[njd][3] + x2.y) * iv_hi;
            size_t off1 = ((size_t)(b * SS) + qglo) * D + h * DH + col;
            size_t off2 = ((size_t)(b * SS) + qghi) * D + h * DH + col;
            *(uint32_t*)(Oh + off1) = pack_hi2(o0, o1);
            *(uint32_t*)(Ol + off1) = pack_lo2(o0, o1);
            *(uint32_t*)(Oh + off2) = pack_hi2(o2, o3);
            *(uint32_t*)(Ol + off2) = pack_lo2(o2, o3);
        }
    }
}

// ---------------- LayerNorm; fp32 out + optional bf16 hi/lo planes ----------------
__global__ __launch_bounds__(256) void ln_kernel(
    const float* __restrict__ X, const float* __restrict__ g,
    const float* __restrict__ be, float* __restrict__ Y,
    bf16* __restrict__ Yh, bf16* __restrict__ Yl)
{
    __shared__ float ss[8], ssq[8];
    int row = blockIdx.x;
    int tid = threadIdx.x;
    const float* x = X + (size_t)row * D;
    float4 v = ((const float4*)x)[tid];
    float s = v.x + v.y + v.z + v.w;
    float sq = v.x * v.x + v.y * v.y + v.z * v.z + v.w * v.w;
#pragma unroll
    for (int o = 16; o; o >>= 1) {
        s += __shfl_xor_sync(0xffffffffu, s, o);
        sq += __shfl_xor_sync(0xffffffffu, sq, o);
    }
    int w = tid >> 5;
    if ((tid & 31) == 0) { ss[w] = s; ssq[w] = sq; }
    __syncthreads();
    if (tid < 32) {
        s = (tid < 8) ? ss[tid] : 0.f;
        sq = (tid < 8) ? ssq[tid] : 0.f;
#pragma unroll
        for (int o = 4; o; o >>= 1) {
            s += __shfl_xor_sync(0xffffffffu, s, o);
            sq += __shfl_xor_sync(0xffffffffu, sq, o);
        }
        if (tid == 0) { ss[0] = s; ssq[0] = sq; }
    }
    __syncthreads();
    float mean = ss[0] * (1.f / D);
    float var = ssq[0] * (1.f / D) - mean * mean;
    float inv = rsqrtf(var + 1e-6f);
    float4 gg = ((const float4*)g)[tid];
    float4 bb = ((const float4*)be)[tid];
    float4 o;
    o.x = (v.x - mean) * inv * gg.x + bb.x;
    o.y = (v.y - mean) * inv * gg.y + bb.y;
    o.z = (v.z - mean) * inv * gg.z + bb.z;
    o.w = (v.w - mean) * inv * gg.w + bb.w;
    ((float4*)(Y + (size_t)row * D))[tid] = o;
    if (Yh) {
        uint2 hv, lv;
        hv.x = pack_hi2(o.x, o.y); hv.y = pack_hi2(o.z, o.w);
        lv.x = pack_lo2(o.x, o.y); lv.y = pack_lo2(o.z, o.w);
        size_t off = (size_t)row * D + tid * 4;
        *(uint2*)(Yh + off) = hv;
        *(uint2*)(Yl + off) = lv;
    }
}

// ---------------- host orchestration ----------------
extern "C" void kernel_launch(void* const* d_in, const int* in_sizes, int n_in,
                              void* d_out, int out_size)
{
    const float* x_in = (const float*)d_in[0];
    const int*   rid  = (const int*)d_in[1];
    const float* Wq = (const float*)d_in[2];
    const float* bq = (const float*)d_in[3];
    const float* Wk = (const float*)d_in[4];
    const float* bk = (const float*)d_in[5];
    const float* Wv = (const float*)d_in[6];
    const float* bv = (const float*)d_in[7];
    const float* Wo = (const float*)d_in[8];
    const float* bo = (const float*)d_in[9];
    const float* Erel = (const float*)d_in[10];
    const float* Brel = (const float*)d_in[11];
    const float* g1  = (const float*)d_in[12];
    const float* be1 = (const float*)d_in[13];
    const float* g2  = (const float*)d_in[14];
    const float* be2 = (const float*)d_in[15];
    const float* W1 = (const float*)d_in[16];
    const float* b1 = (const float*)d_in[17];
    const float* W2 = (const float*)d_in[18];
    const float* b2 = (const float*)d_in[19];

    float *q, *t, *ffin, *xg, *qe;
    cudaGetSymbolAddress((void**)&q, g_q);
    cudaGetSymbolAddress((void**)&t, g_t);
    cudaGetSymbolAddress((void**)&ffin, g_ffin);
    cudaGetSymbolAddress((void**)&xg, g_x);
    cudaGetSymbolAddress((void**)&qe, g_qE);

    bf16 *wqh,*wql,*wkh,*wkl,*wvh,*wvl,*woh,*wol,*w1h,*w1l,*w2h,*w2l;
    bf16 *xh,*xl,*qph,*qpl,*kph,*kpl,*vph,*vpl,*ah,*al,*fh,*fl,*hh,*hl;
    cudaGetSymbolAddress((void**)&wqh, g_wqh); cudaGetSymbolAddress((void**)&wql, g_wql);
    cudaGetSymbolAddress((void**)&wkh, g_wkh); cudaGetSymbolAddress((void**)&wkl, g_wkl);
    cudaGetSymbolAddress((void**)&wvh, g_wvh); cudaGetSymbolAddress((void**)&wvl, g_wvl);
    cudaGetSymbolAddress((void**)&woh, g_woh); cudaGetSymbolAddress((void**)&wol, g_wol);
    cudaGetSymbolAddress((void**)&w1h, g_w1h); cudaGetSymbolAddress((void**)&w1l, g_w1l);
    cudaGetSymbolAddress((void**)&w2h, g_w2h); cudaGetSymbolAddress((void**)&w2l, g_w2l);
    cudaGetSymbolAddress((void**)&xh, g_xh);   cudaGetSymbolAddress((void**)&xl, g_xl);
    cudaGetSymbolAddress((void**)&qph, g_qph); cudaGetSymbolAddress((void**)&qpl, g_qpl);
    cudaGetSymbolAddress((void**)&kph, g_kph); cudaGetSymbolAddress((void**)&kpl, g_kpl);
    cudaGetSymbolAddress((void**)&vph, g_vph); cudaGetSymbolAddress((void**)&vpl, g_vpl);
    cudaGetSymbolAddress((void**)&ah, g_ah);   cudaGetSymbolAddress((void**)&al, g_al);
    cudaGetSymbolAddress((void**)&fh, g_fh);   cudaGetSymbolAddress((void**)&fl, g_fl);
    cudaGetSymbolAddress((void**)&hh, g_hh);   cudaGetSymbolAddress((void**)&hl, g_hl);

    cudaFuncSetAttribute(gemm_bf, cudaFuncAttributeMaxDynamicSharedMemorySize, GEMM_SMEM);
    cudaFuncSetAttribute(attn_mma, cudaFuncAttributeMaxDynamicSharedMemorySize, ATT_SMEM);

    // ---- pre-split weights [K][N] and layer-0 input ----
    {
        int nDD = NL * D * D / 4;
        int nDF = (int)((size_t)NL * D * FF / 4);
        int nX  = BS * D / 4;
        split_kernel<<<(nDD + 255) / 256, 256>>>(Wq, wqh, wql, nDD);
        split_kernel<<<(nDD + 255) / 256, 256>>>(Wk, wkh, wkl, nDD);
        split_kernel<<<(nDD + 255) / 256, 256>>>(Wv, wvh, wvl, nDD);
        split_kernel<<<(nDD + 255) / 256, 256>>>(Wo, woh, wol, nDD);
        split_kernel<<<(nDF + 255) / 256, 256>>>(W1, w1h, w1l, nDF);
        split_kernel<<<(nDF + 255) / 256, 256>>>(W2, w2h, w2l, nDF);
        split_kernel<<<(nX + 255) / 256, 256>>>(x_in, xh, xl, nX);
    }

    const float* Xf = x_in;
    for (int l = 0; l < NL; l++) {
        const size_t wDD = (size_t)l * D * D;
        const size_t wDF = (size_t)l * D * FF;
        // fused QKV: q -> fp32 + planes; k,v -> planes only
        gemm_bf<<<dim3(8, 32, 3), 256, GEMM_SMEM>>>(xh, xl,
            wqh + wDD, wql + wDD, wkh + wDD, wkl + wDD, wvh + wDD, wvl + wDD,
            bq + l * D, bk + l * D, bv + l * D, nullptr,
            q, nullptr, nullptr,
            qph, qpl, kph, kpl, vph, vpl, BS, D, D, 0);
        qe_kernel<<<BS, 256>>>(q, Erel + (size_t)l * NB * DH, qe);
        attn_mma<<<dim3(16, 16, 4), 256, ATT_SMEM>>>(qph, qpl, kph, kpl, vph, vpl,
            qe, Brel + (size_t)l * H * NB, rid, ah, al);
        // Wo + residual
        gemm_bf<<<dim3(8, 32, 1), 256, GEMM_SMEM>>>(ah, al,
            woh + wDD, wol + wDD, nullptr, nullptr, nullptr, nullptr,
            bo + l * D, nullptr, nullptr, Xf,
            t, nullptr, nullptr,
            nullptr, nullptr, nullptr, nullptr, nullptr, nullptr, BS, D, D, 0);
        ln_kernel<<<BS, 256>>>(t, g1 + l * D, be1 + l * D, ffin, fh, fl);
        // W1 + relu -> planes only
        gemm_bf<<<dim3(32, 32, 1), 256, GEMM_SMEM>>>(fh, fl,
            w1h + wDF, w1l + wDF, nullptr, nullptr, nullptr, nullptr,
            b1 + (size_t)l * FF, nullptr, nullptr, nullptr,
            nullptr, nullptr, nullptr,
            hh, hl, nullptr, nullptr, nullptr, nullptr, BS, FF, D, 1);
        // W2 + residual
        gemm_bf<<<dim3(8, 32, 1), 256, GEMM_SMEM>>>(hh, hl,
            w2h + wDF, w2l + wDF, nullptr, nullptr, nullptr, nullptr,
            b2 + l * D, nullptr, nullptr, ffin,
            t, nullptr, nullptr,
            nullptr, nullptr, nullptr, nullptr, nullptr, nullptr, BS, D, FF, 0);
        float* out = (l == NL - 1) ? (float*)d_out : xg;
        bf16* oh = (l == NL - 1) ? nullptr : xh;
        bf16* ol = (l == NL - 1) ? nullptr : xl;
        ln_kernel<<<BS, 256>>>(t, g2 + l * D, be2 + l * D, out, oh, ol);
        Xf = xg;
    }
}